// round 7
// baseline (speedup 1.0000x reference)
#include <cuda_runtime.h>
#include <cstdint>
#include <math.h>

// ---------------------------------------------------------------------------
// Problem constants
// ---------------------------------------------------------------------------
#define BB   128
#define TT   100
#define HIDN 512
#define G3   1536

// GRU tiling
#define GJT  16       // hidden-col tile
#define GNC  128      // CTAs
#define GTH  256      // threads (8 warps)

// ---------------------------------------------------------------------------
// Device scratch
// ---------------------------------------------------------------------------
__device__ float g_x1  [(size_t)BB * 64 * 576];   // conv1 out, NCHW
__device__ float g_x2  [(size_t)BB * 64 * 81];    // conv2 out, NCHW
__device__ float g_flat[(size_t)BB * 1024];       // conv3 out == flatten
__device__ float g_fc1 [(size_t)BB * 1024];
__device__ float g_fc2 [(size_t)BB * 512];
__device__ __align__(16) float g_h[2][(size_t)BB * HIDN];
__device__ unsigned g_flag[4][32][32];            // [group][cta][pad 128B]

// ---------------------------------------------------------------------------
// Helpers
// ---------------------------------------------------------------------------
__device__ __forceinline__ float tf32f(float x) {
    unsigned u;
    asm("cvt.rna.tf32.f32 %0, %1;" : "=r"(u) : "f"(x));
    return __uint_as_float(u);
}

__device__ __forceinline__ void mma8(float* c,
                                     float a0, float a1, float a2, float a3,
                                     float b0, float b1) {
    unsigned A0 = __float_as_uint(a0), A1 = __float_as_uint(a1);
    unsigned A2 = __float_as_uint(a2), A3 = __float_as_uint(a3);
    unsigned B0 = __float_as_uint(b0), B1 = __float_as_uint(b1);
    asm volatile(
        "mma.sync.aligned.m16n8k8.row.col.f32.tf32.tf32.f32 "
        "{%0,%1,%2,%3}, {%4,%5,%6,%7}, {%8,%9}, {%0,%1,%2,%3};"
        : "+f"(c[0]), "+f"(c[1]), "+f"(c[2]), "+f"(c[3])
        : "r"(A0), "r"(A1), "r"(A2), "r"(A3), "r"(B0), "r"(B1));
}

__device__ __forceinline__ void cpa4(unsigned dst, const void* src, int sz) {
    asm volatile("cp.async.ca.shared.global [%0], [%1], 4, %2;\n"
                 :: "r"(dst), "l"(src), "r"(sz));
}
__device__ __forceinline__ void cpa16(unsigned dst, const void* src) {
    asm volatile("cp.async.ca.shared.global [%0], [%1], 16;\n"
                 :: "r"(dst), "l"(src));
}
__device__ __forceinline__ void cpa_commit() {
    asm volatile("cp.async.commit_group;\n");
}
template<int N> __device__ __forceinline__ void cpa_wait() {
    asm volatile("cp.async.wait_group %0;\n" :: "n"(N));
}

// ---------------------------------------------------------------------------
// Fused im2col + tf32 GEMM conv (cp.async double-buffered):
//   out[b, oc, p] = relu(conv(src) + bias); stride 3, pad 2; OC = 64.
// ---------------------------------------------------------------------------
template<int KTOT, int KW, int CIN, int IH, int KS, int OW>
__global__ void __launch_bounds__(256, 1)
convgemm_k(const float* __restrict__ src,
           const float* __restrict__ W,
           const float* __restrict__ bias,
           float* __restrict__ C) {
    constexpr int PIX = OW * OW;
    constexpr int NIT = KTOT / 16;
    __shared__ __align__(16) float As[2][128 * 20];
    __shared__ __align__(16) float Bs[2][64 * 20];

    int tid = threadIdx.x;
    int warp = tid >> 5, lane = tid & 31;
    int wm = warp >> 1;
    int wn = warp & 1;
    int m0 = blockIdx.x * 128;
    int kk = tid & 15;

    // hoisted per-thread A-row geometry
    int iy0[8], ix0[8], sb[8], mloc[8];
#pragma unroll
    for (int i = 0; i < 8; i++) {
        mloc[i] = i * 16 + (tid >> 4);
        int m = m0 + mloc[i];
        int b = m / PIX, pix = m % PIX;
        int oy = pix / OW, ox = pix % OW;
        iy0[i] = oy * 3 - 2;
        ix0[i] = ox * 3 - 2;
        sb[i] = b * CIN * IH * IH;
    }

    unsigned AsA = (unsigned)__cvta_generic_to_shared(&As[0][0]);
    unsigned BsA = (unsigned)__cvta_generic_to_shared(&Bs[0][0]);

    auto stage = [&](int st, int bf) {
        int k = st * 16 + kk;
        bool kok = (k < KW);
        int ci = 0, ky = 0, kx = 0;
        if (kok) {
            ci = k / (KS * KS);
            int rem = k % (KS * KS);
            ky = rem / KS; kx = rem % KS;
        }
#pragma unroll
        for (int i = 0; i < 8; i++) {
            int iy = iy0[i] + ky, ix = ix0[i] + kx;
            bool ok = kok && iy >= 0 && iy < IH && ix >= 0 && ix < IH;
            const float* s = ok ? (src + sb[i] + ((size_t)ci * IH + iy) * IH + ix)
                                : src;
            cpa4(AsA + (unsigned)(bf * 128 * 20 + mloc[i] * 20 + kk) * 4, s,
                 ok ? 4 : 0);
        }
#pragma unroll
        for (int i = 0; i < 4; i++) {
            int e = i * 256 + tid;
            int n = e >> 4, kl = e & 15;
            int kg = st * 16 + kl;
            bool ok = (kg < KW);
            const float* s = ok ? (W + (size_t)n * KW + kg) : W;
            cpa4(BsA + (unsigned)(bf * 64 * 20 + n * 20 + kl) * 4, s, ok ? 4 : 0);
        }
        cpa_commit();
    };

    float acc[2][4][4];
#pragma unroll
    for (int a = 0; a < 2; a++)
#pragma unroll
        for (int b = 0; b < 4; b++)
#pragma unroll
            for (int c = 0; c < 4; c++) acc[a][b][c] = 0.f;

    stage(0, 0);

    for (int it = 0; it < NIT; it++) {
        int bf = it & 1;
        if (it + 1 < NIT) { stage(it + 1, bf ^ 1); cpa_wait<1>(); }
        else              { cpa_wait<0>(); }
        __syncthreads();

        const float* Asb = &As[bf][0];
        const float* Bsb = &Bs[bf][0];
#pragma unroll
        for (int kq = 0; kq < 2; kq++) {
            int kb = kq * 8;
#pragma unroll
            for (int mt = 0; mt < 2; mt++) {
                int r = wm * 32 + mt * 16 + (lane >> 2);
                int c = kb + (lane & 3);
                float a0 = Asb[r * 20 + c];
                float a1 = Asb[(r + 8) * 20 + c];
                float a2 = Asb[r * 20 + c + 4];
                float a3 = Asb[(r + 8) * 20 + c + 4];
#pragma unroll
                for (int nt = 0; nt < 4; nt++) {
                    int n = wn * 32 + nt * 8 + (lane >> 2);
                    float b0 = Bsb[n * 20 + kb + (lane & 3)];
                    float b1 = Bsb[n * 20 + kb + 4 + (lane & 3)];
                    mma8(acc[mt][nt], a0, a1, a2, a3, b0, b1);
                }
            }
        }
        __syncthreads();
    }

    // epilogue: relu + NCHW scatter
#pragma unroll
    for (int mt = 0; mt < 2; mt++) {
#pragma unroll
        for (int nt = 0; nt < 4; nt++) {
            int r = m0 + wm * 32 + mt * 16 + (lane >> 2);
            int cc = wn * 32 + nt * 8 + 2 * (lane & 3);
#pragma unroll
            for (int q = 0; q < 4; q++) {
                int rr = r + (q >> 1) * 8;
                int cn = cc + (q & 1);
                float v = fmaxf(acc[mt][nt][q] + bias[cn], 0.f);
                int b = rr / PIX, p = rr % PIX;
                C[((size_t)b * 64 + cn) * PIX + p] = v;
            }
        }
    }
}

// ---------------------------------------------------------------------------
// FC tf32 GEMM (cp.async double-buffered): C[M,N] = A[M,K] * W[N,K]^T + bias
//   M == 128 (grid.x == 1), Ntot % 64 == 0, K % 16 == 0.
// ---------------------------------------------------------------------------
__global__ void __launch_bounds__(256, 1)
gemm_k(const float* __restrict__ A, int lda,
       const float* __restrict__ W, int ldw,
       const float* __restrict__ bias,
       float* __restrict__ C,
       int K, int Ntot, int relu) {
    __shared__ __align__(16) float As[2][128 * 20];
    __shared__ __align__(16) float Bs[2][64 * 20];

    int tid = threadIdx.x;
    int warp = tid >> 5, lane = tid & 31;
    int wm = warp >> 1;
    int wn = warp & 1;
    int m0 = blockIdx.x * 128;
    int n0 = blockIdx.y * 64;

    unsigned AsA = (unsigned)__cvta_generic_to_shared(&As[0][0]);
    unsigned BsA = (unsigned)__cvta_generic_to_shared(&Bs[0][0]);

    auto stage = [&](int st, int bf) {
#pragma unroll
        for (int i = 0; i < 2; i++) {
            int e = i * 256 + tid;
            int m = e >> 2, c4 = e & 3;
            cpa16(AsA + (unsigned)(bf * 128 * 20 + m * 20 + c4 * 4) * 4,
                  A + (size_t)(m0 + m) * lda + st * 16 + c4 * 4);
        }
        {
            int n = tid >> 2, c4 = tid & 3;
            cpa16(BsA + (unsigned)(bf * 64 * 20 + n * 20 + c4 * 4) * 4,
                  W + (size_t)(n0 + n) * ldw + st * 16 + c4 * 4);
        }
        cpa_commit();
    };

    float acc[2][4][4];
#pragma unroll
    for (int a = 0; a < 2; a++)
#pragma unroll
        for (int b = 0; b < 4; b++)
#pragma unroll
            for (int c = 0; c < 4; c++) acc[a][b][c] = 0.f;

    int NIT = K / 16;
    stage(0, 0);

    for (int it = 0; it < NIT; it++) {
        int bf = it & 1;
        if (it + 1 < NIT) { stage(it + 1, bf ^ 1); cpa_wait<1>(); }
        else              { cpa_wait<0>(); }
        __syncthreads();

        const float* Asb = &As[bf][0];
        const float* Bsb = &Bs[bf][0];
#pragma unroll
        for (int kq = 0; kq < 2; kq++) {
            int kb = kq * 8;
#pragma unroll
            for (int mt = 0; mt < 2; mt++) {
                int r = wm * 32 + mt * 16 + (lane >> 2);
                int c = kb + (lane & 3);
                float a0 = Asb[r * 20 + c];
                float a1 = Asb[(r + 8) * 20 + c];
                float a2 = Asb[r * 20 + c + 4];
                float a3 = Asb[(r + 8) * 20 + c + 4];
#pragma unroll
                for (int nt = 0; nt < 4; nt++) {
                    int n = wn * 32 + nt * 8 + (lane >> 2);
                    float b0 = Bsb[n * 20 + kb + (lane & 3)];
                    float b1 = Bsb[n * 20 + kb + 4 + (lane & 3)];
                    mma8(acc[mt][nt], a0, a1, a2, a3, b0, b1);
                }
            }
        }
        __syncthreads();
    }

#pragma unroll
    for (int mt = 0; mt < 2; mt++) {
#pragma unroll
        for (int nt = 0; nt < 4; nt++) {
            int r = m0 + wm * 32 + mt * 16 + (lane >> 2);
            int cc = n0 + wn * 32 + nt * 8 + 2 * (lane & 3);
#pragma unroll
            for (int q = 0; q < 4; q++) {
                int rr = r + (q >> 1) * 8;
                int cn = cc + (q & 1);
                float v = acc[mt][nt][q] + bias[cn];
                if (relu) v = fmaxf(v, 0.f);
                C[(size_t)rr * Ntot + cn] = v;
            }
        }
    }
}

// ---------------------------------------------------------------------------
// Persistent GRU. 128 CTAs x 256 threads, 4 independent groups of 32 CTAs.
// Fragment-major smem: A-frags (h) as float4/lane, B-frags (w_hh) as float2.
// gi computed inline from actions (ACT=2): no gi buffer at all.
// ---------------------------------------------------------------------------
#define HSF_FLOATS (2 * 64 * 32 * 4)     // 16384
#define WSF_FLOATS (6 * 64 * 32 * 2)     // 24576
#define GS_FLOATS  (32 * 48)             // 1536

__global__ void __launch_bounds__(GTH, 1)
gru_k(const float* __restrict__ actions,
      const float* __restrict__ w_ih,
      const float* __restrict__ w_hh,
      const float* __restrict__ b_ih,
      const float* __restrict__ b_hh,
      float* __restrict__ out,
      float* __restrict__ hT) {
    extern __shared__ float sm[];
    float* HsF = sm;
    float* WsF = sm + HSF_FLOATS;
    float* Gs  = sm + HSF_FLOATS + WSF_FLOATS;

    int tid = threadIdx.x;
    int warp = tid >> 5, lane = tid & 31;
    int wm = warp & 1;
    int wn = warp >> 1;
    int nsub = (wn < 2) ? 2 : 1;
    int sub0 = (wn < 2) ? wn * 2 : wn + 2;

    int cta = blockIdx.x;
    int ib = cta >> 5;
    int jg = cta & 31;
    int j0 = jg * GJT;

    unsigned fbase = *(volatile unsigned*)&g_flag[ib][jg][0];

    // per-thread gate-fusion constants (2 output elements per thread)
    int e0 = tid, e1 = tid + GTH;
    int bl0 = e0 >> 4, jj0 = e0 & 15, bg0 = ib * 32 + bl0, jA = j0 + jj0;
    int bl1 = e1 >> 4, jj1 = e1 & 15, bg1 = ib * 32 + bl1, jB = j0 + jj1;
    float bhrA = b_hh[jA], bhiA = b_hh[512 + jA], bhnA = b_hh[1024 + jA];
    float bhrB = b_hh[jB], bhiB = b_hh[512 + jB], bhnB = b_hh[1024 + jB];
    float wrA0 = w_ih[2 * jA],          wrA1 = w_ih[2 * jA + 1];
    float wzA0 = w_ih[2 * (512 + jA)],  wzA1 = w_ih[2 * (512 + jA) + 1];
    float wnA0 = w_ih[2 * (1024 + jA)], wnA1 = w_ih[2 * (1024 + jA) + 1];
    float wrB0 = w_ih[2 * jB],          wrB1 = w_ih[2 * jB + 1];
    float wzB0 = w_ih[2 * (512 + jB)],  wzB1 = w_ih[2 * (512 + jB) + 1];
    float wnB0 = w_ih[2 * (1024 + jB)], wnB1 = w_ih[2 * (1024 + jB) + 1];
    float birA = b_ih[jA], bizA = b_ih[512 + jA], binA = b_ih[1024 + jA];
    float birB = b_ih[jB], bizB = b_ih[512 + jB], binB = b_ih[1024 + jB];

    // Stage w_hh fragments once (RNA tf32): WsF[s][k8][lane][2]
#pragma unroll 4
    for (int i = 0; i < 48; i++) {
        int idx = i * GTH + tid;
        int ln = idx & 31;
        int k8 = (idx >> 5) & 63;
        int s  = idx >> 11;               // 0..5
        int n48 = s * 8 + (ln >> 2);
        int gate = n48 >> 4, jj = n48 & 15;
        const float* wrow = w_hh + ((size_t)gate * 512 + j0 + jj) * 512;
        int c = k8 * 8 + (ln & 3);
        float2 bf;
        bf.x = tf32f(wrow[c]);
        bf.y = tf32f(wrow[c + 4]);
        *(float2*)&WsF[(size_t)idx * 2] = bf;
    }

    for (int t = 0; t < TT; t++) {
        const float* hcur = g_h[t & 1];
        float* hnxt = g_h[(t + 1) & 1];

        // prefetch actions + own h values for the gate phase
        const float* ap0 = actions + ((size_t)bg0 * TT + t) * 2;
        const float* ap1 = actions + ((size_t)bg1 * TT + t) * 2;
        float a00 = __ldg(ap0), a01 = __ldg(ap0 + 1);
        float a10 = __ldg(ap1), a11 = __ldg(ap1 + 1);
        float hv0 = __ldcg(hcur + (size_t)bg0 * HIDN + jA);
        float hv1 = __ldcg(hcur + (size_t)bg1 * HIDN + jB);

        // stage h tile as A-fragments: HsF[wm][k8][lane][4]
        const float* hbase = hcur + (size_t)ib * 32 * HIDN;
#pragma unroll 4
        for (int i = 0; i < 16; i++) {
            int idx = i * GTH + tid;
            int ln = idx & 31;
            int k8 = (idx >> 5) & 63;
            int w2 = idx >> 11;           // 0..1
            int r = w2 * 16 + (ln >> 2);
            int c = k8 * 8 + (ln & 3);
            float4 f;
            f.x = __ldcg(hbase + (size_t)r * HIDN + c);
            f.y = __ldcg(hbase + (size_t)(r + 8) * HIDN + c);
            f.z = __ldcg(hbase + (size_t)r * HIDN + c + 4);
            f.w = __ldcg(hbase + (size_t)(r + 8) * HIDN + c + 4);
            *(float4*)&HsF[(size_t)idx * 4] = f;
        }
        __syncthreads();

        float acc[2][4];
#pragma unroll
        for (int a = 0; a < 2; a++)
#pragma unroll
            for (int c = 0; c < 4; c++) acc[a][c] = 0.f;

        const float* afp = HsF + ((size_t)(wm * 64) * 32 + lane) * 4;
        const float* bfp0 = WsF + ((size_t)(sub0 * 64) * 32 + lane) * 2;
        const float* bfp1 = WsF + ((size_t)((sub0 + 1) * 64) * 32 + lane) * 2;

#pragma unroll 8
        for (int k8 = 0; k8 < 64; k8++) {
            float4 af = *(const float4*)(afp + (size_t)k8 * 128);
            float2 b0 = *(const float2*)(bfp0 + (size_t)k8 * 64);
            mma8(acc[0], af.x, af.y, af.z, af.w, b0.x, b0.y);
            if (nsub == 2) {
                float2 b1 = *(const float2*)(bfp1 + (size_t)k8 * 64);
                mma8(acc[1], af.x, af.y, af.z, af.w, b1.x, b1.y);
            }
        }

        // dump gh fragments for gate fusion
#pragma unroll
        for (int i = 0; i < 2; i++) {
            if (i < nsub) {
                int s = sub0 + i;
                int r = wm * 16 + (lane >> 2);
                int c = s * 8 + 2 * (lane & 3);
                Gs[r * 48 + c]           = acc[i][0];
                Gs[r * 48 + c + 1]       = acc[i][1];
                Gs[(r + 8) * 48 + c]     = acc[i][2];
                Gs[(r + 8) * 48 + c + 1] = acc[i][3];
            }
        }
        __syncthreads();

        // fused gates (exact f32 state update; gi inline from actions)
        {
            float gr = a00 * wrA0 + a01 * wrA1 + birA;
            float gz = a00 * wzA0 + a01 * wzA1 + bizA;
            float gn = a00 * wnA0 + a01 * wnA1 + binA;
            float ghr = Gs[bl0 * 48 + jj0]      + bhrA;
            float ghi = Gs[bl0 * 48 + 16 + jj0] + bhiA;
            float ghn = Gs[bl0 * 48 + 32 + jj0] + bhnA;
            float r = 1.f / (1.f + expf(-(gr + ghr)));
            float z = 1.f / (1.f + expf(-(gz + ghi)));
            float n = tanhf(gn + r * ghn);
            float hy = n + z * (hv0 - n);
            hnxt[(size_t)bg0 * HIDN + jA] = hy;
            out[((size_t)bg0 * TT + t) * HIDN + jA] = hy;
            if (t == TT - 1) hT[(size_t)bg0 * HIDN + jA] = hy;
        }
        {
            float gr = a10 * wrB0 + a11 * wrB1 + birB;
            float gz = a10 * wzB0 + a11 * wzB1 + bizB;
            float gn = a10 * wnB0 + a11 * wnB1 + binB;
            float ghr = Gs[bl1 * 48 + jj1]      + bhrB;
            float ghi = Gs[bl1 * 48 + 16 + jj1] + bhiB;
            float ghn = Gs[bl1 * 48 + 32 + jj1] + bhnB;
            float r = 1.f / (1.f + expf(-(gr + ghr)));
            float z = 1.f / (1.f + expf(-(gz + ghi)));
            float n = tanhf(gn + r * ghn);
            float hy = n + z * (hv1 - n);
            hnxt[(size_t)bg1 * HIDN + jB] = hy;
            out[((size_t)bg1 * TT + t) * HIDN + jB] = hy;
            if (t == TT - 1) hT[(size_t)bg1 * HIDN + jB] = hy;
        }

        // group barrier (32 CTAs of this ib group); skip after last step
        if (t < TT - 1) {
            __threadfence();
            __syncthreads();
            if (tid == 0)
                *(volatile unsigned*)&g_flag[ib][jg][0] = fbase + (unsigned)(t + 1);
            if (tid < 32) {
                while ((*(volatile unsigned*)&g_flag[ib][tid][0] - fbase)
                       < (unsigned)(t + 1)) { }
            }
            __syncthreads();
        }
    }
}

// ---------------------------------------------------------------------------
// Host launch
// ---------------------------------------------------------------------------
extern "C" void kernel_launch(void* const* d_in, const int* in_sizes, int n_in,
                              void* d_out, int out_size) {
    const float* images  = (const float*)d_in[0];
    const float* actions = (const float*)d_in[1];
    const float* cw1 = (const float*)d_in[2];
    const float* cb1 = (const float*)d_in[3];
    const float* cw2 = (const float*)d_in[4];
    const float* cb2 = (const float*)d_in[5];
    const float* cw3 = (const float*)d_in[6];
    const float* cb3 = (const float*)d_in[7];
    const float* fw1 = (const float*)d_in[8];
    const float* fb1 = (const float*)d_in[9];
    const float* fw2 = (const float*)d_in[10];
    const float* fb2 = (const float*)d_in[11];
    const float* fw3 = (const float*)d_in[12];
    const float* fb3 = (const float*)d_in[13];
    const float* w_ih = (const float*)d_in[14];
    const float* w_hh = (const float*)d_in[15];
    const float* b_ih = (const float*)d_in[16];
    const float* b_hh = (const float*)d_in[17];

    float *x1, *x2, *flat, *fc1, *fc2, *hbuf;
    cudaGetSymbolAddress((void**)&x1,   g_x1);
    cudaGetSymbolAddress((void**)&x2,   g_x2);
    cudaGetSymbolAddress((void**)&flat, g_flat);
    cudaGetSymbolAddress((void**)&fc1,  g_fc1);
    cudaGetSymbolAddress((void**)&fc2,  g_fc2);
    cudaGetSymbolAddress((void**)&hbuf, g_h);

    const int gru_smem = (HSF_FLOATS + WSF_FLOATS + GS_FLOATS) * 4;
    cudaFuncSetAttribute(gru_k, cudaFuncAttributeMaxDynamicSharedMemorySize,
                         gru_smem);

    // encoder: fused im2col+GEMM convs (pipelined)
    convgemm_k<80, 75, 3, 72, 5, 24><<<576, 256>>>(images, cw1, cb1, x1);
    convgemm_k<576, 576, 64, 24, 3, 9><<<81, 256>>>(x1, cw2, cb2, x2);
    convgemm_k<576, 576, 64, 9, 3, 4><<<16, 256>>>(x2, cw3, cb3, flat);

    // FC head (pipelined)
    gemm_k<<<dim3(1, 16), 256>>>(flat, 1024, fw1, 1024, fb1, fc1, 1024, 1024, 1);
    gemm_k<<<dim3(1, 8), 256>>>(fc1, 1024, fw2, 1024, fb2, fc2, 1024, 512, 1);
    gemm_k<<<dim3(1, 8), 256>>>(fc2, 512, fw3, 512, fb3, hbuf, 512, 512, 0);

    // persistent GRU (gi computed inline)
    float* out = (float*)d_out;
    float* hT = out + (size_t)BB * TT * HIDN;
    gru_k<<<GNC, GTH, gru_smem>>>(actions, w_ih, w_hh, b_ih, b_hh, out, hT);
}

// round 10
// speedup vs baseline: 1.4339x; 1.4339x over previous
#include <cuda_runtime.h>
#include <cstdint>
#include <math.h>

// ---------------------------------------------------------------------------
// Problem constants
// ---------------------------------------------------------------------------
#define BB   128
#define TT   100
#define HIDN 512
#define G3   1536

// GRU tiling
#define GJT  16       // hidden-col tile
#define GNC  128      // CTAs
#define GTH  256      // threads (8 warps)
#define HF_GROUP 16384   // floats per group fragment tile (32x512)

// ---------------------------------------------------------------------------
// Device scratch
// ---------------------------------------------------------------------------
__device__ float g_x1  [(size_t)BB * 64 * 576];   // conv1 out, NCHW
__device__ float g_x2  [(size_t)BB * 64 * 81];    // conv2 out, NCHW
__device__ float g_flat[(size_t)BB * 1024];       // conv3 out == flatten
__device__ float g_fc1 [(size_t)BB * 1024];
__device__ float g_fc2 [(size_t)BB * 512];
__device__ __align__(16) float g_hf[2][4 * HF_GROUP];  // h in A-fragment order
__device__ unsigned g_flag[4][32][32];            // [group][cta][pad 128B]

// ---------------------------------------------------------------------------
// Helpers
// ---------------------------------------------------------------------------
__device__ __forceinline__ float tf32f(float x) {
    unsigned u;
    asm("cvt.rna.tf32.f32 %0, %1;" : "=r"(u) : "f"(x));
    return __uint_as_float(u);
}

__device__ __forceinline__ void mma8(float* c,
                                     float a0, float a1, float a2, float a3,
                                     float b0, float b1) {
    unsigned A0 = __float_as_uint(a0), A1 = __float_as_uint(a1);
    unsigned A2 = __float_as_uint(a2), A3 = __float_as_uint(a3);
    unsigned B0 = __float_as_uint(b0), B1 = __float_as_uint(b1);
    asm volatile(
        "mma.sync.aligned.m16n8k8.row.col.f32.tf32.tf32.f32 "
        "{%0,%1,%2,%3}, {%4,%5,%6,%7}, {%8,%9}, {%0,%1,%2,%3};"
        : "+f"(c[0]), "+f"(c[1]), "+f"(c[2]), "+f"(c[3])
        : "r"(A0), "r"(A1), "r"(A2), "r"(A3), "r"(B0), "r"(B1));
}

__device__ __forceinline__ void cpa16(unsigned dst, const void* src) {
    asm volatile("cp.async.cg.shared.global [%0], [%1], 16;\n"
                 :: "r"(dst), "l"(src));
}
__device__ __forceinline__ void cpa_commit() {
    asm volatile("cp.async.commit_group;\n");
}
template<int N> __device__ __forceinline__ void cpa_wait() {
    asm volatile("cp.async.wait_group %0;\n" :: "n"(N));
}

// position of element (bl, j) inside a group's A-fragment tile
__device__ __forceinline__ int hfrag_idx(int bl, int j) {
    int w2 = bl >> 4;
    int k8 = j >> 3;
    int ln = ((bl & 7) << 2) | (j & 3);
    int slot = ((bl >> 3) & 1) | (((j >> 2) & 1) << 1);
    return (((w2 * 64 + k8) << 5) + ln) * 4 + slot;
}

// ---------------------------------------------------------------------------
// Fused im2col + tf32 GEMM conv, 4-stage cp.async pipeline.
//   out[b, oc, p] = relu(conv(src) + bias); stride 3, pad 2; OC = 64.
// ---------------------------------------------------------------------------
#define ENC_STG 4
#define ENC_AS  (128 * 20)
#define ENC_BS  (64 * 20)
#define ENC_SMEM ((ENC_STG * (ENC_AS + ENC_BS)) * 4)

template<int KTOT, int KW, int CIN, int IH, int KS, int OW>
__global__ void __launch_bounds__(256, 1)
convgemm_k(const float* __restrict__ src,
           const float* __restrict__ W,
           const float* __restrict__ bias,
           float* __restrict__ C) {
    constexpr int PIX = OW * OW;
    constexpr int NIT = KTOT / 16;
    extern __shared__ float smx[];
    float* As = smx;                       // [4][128*20]
    float* Bs = smx + ENC_STG * ENC_AS;    // [4][64*20]

    int tid = threadIdx.x;
    int warp = tid >> 5, lane = tid & 31;
    int wm = warp >> 1;
    int wn = warp & 1;
    int m0 = blockIdx.x * 128;
    int kk = tid & 15;

    int iy0[8], ix0[8], sb[8], mloc[8];
#pragma unroll
    for (int i = 0; i < 8; i++) {
        mloc[i] = i * 16 + (tid >> 4);
        int m = m0 + mloc[i];
        int b = m / PIX, pix = m % PIX;
        int oy = pix / OW, ox = pix % OW;
        iy0[i] = oy * 3 - 2;
        ix0[i] = ox * 3 - 2;
        sb[i] = b * CIN * IH * IH;
    }

    unsigned AsA = (unsigned)__cvta_generic_to_shared(As);
    unsigned BsA = (unsigned)__cvta_generic_to_shared(Bs);

    auto stage = [&](int st, int bf) {
        int k = st * 16 + kk;
        bool kok = (k < KW);
        int ci = 0, ky = 0, kx = 0;
        if (kok) {
            ci = k / (KS * KS);
            int rem = k % (KS * KS);
            ky = rem / KS; kx = rem % KS;
        }
#pragma unroll
        for (int i = 0; i < 8; i++) {
            int iy = iy0[i] + ky, ix = ix0[i] + kx;
            bool ok = kok && iy >= 0 && iy < IH && ix >= 0 && ix < IH;
            const float* s = ok ? (src + sb[i] + ((size_t)ci * IH + iy) * IH + ix)
                                : src;
            asm volatile("cp.async.ca.shared.global [%0], [%1], 4, %2;\n"
                         :: "r"(AsA + (unsigned)(bf * ENC_AS + mloc[i] * 20 + kk) * 4),
                            "l"(s), "r"(ok ? 4 : 0));
        }
#pragma unroll
        for (int i = 0; i < 4; i++) {
            int e = i * 256 + tid;
            int n = e >> 4, kl = e & 15;
            int kg = st * 16 + kl;
            bool ok = (kg < KW);
            const float* s = ok ? (W + (size_t)n * KW + kg) : W;
            asm volatile("cp.async.ca.shared.global [%0], [%1], 4, %2;\n"
                         :: "r"(BsA + (unsigned)(bf * ENC_BS + n * 20 + kl) * 4),
                            "l"(s), "r"(ok ? 4 : 0));
        }
        cpa_commit();
    };

    float acc[2][4][4];
#pragma unroll
    for (int a = 0; a < 2; a++)
#pragma unroll
        for (int b = 0; b < 4; b++)
#pragma unroll
            for (int c = 0; c < 4; c++) acc[a][b][c] = 0.f;

    stage(0, 0); stage(1, 1); stage(2, 2);

    for (int it = 0; it < NIT; it++) {
        cpa_wait<2>();
        __syncthreads();
        if (it + 3 < NIT) stage(it + 3, (it + 3) & 3);
        else              cpa_commit();          // keep group count advancing

        const float* Asb = As + (it & 3) * ENC_AS;
        const float* Bsb = Bs + (it & 3) * ENC_BS;
#pragma unroll
        for (int kq = 0; kq < 2; kq++) {
            int kb = kq * 8;
#pragma unroll
            for (int mt = 0; mt < 2; mt++) {
                int r = wm * 32 + mt * 16 + (lane >> 2);
                int c = kb + (lane & 3);
                float a0 = Asb[r * 20 + c];
                float a1 = Asb[(r + 8) * 20 + c];
                float a2 = Asb[r * 20 + c + 4];
                float a3 = Asb[(r + 8) * 20 + c + 4];
#pragma unroll
                for (int nt = 0; nt < 4; nt++) {
                    int n = wn * 32 + nt * 8 + (lane >> 2);
                    float b0 = Bsb[n * 20 + kb + (lane & 3)];
                    float b1 = Bsb[n * 20 + kb + 4 + (lane & 3)];
                    mma8(acc[mt][nt], a0, a1, a2, a3, b0, b1);
                }
            }
        }
    }

    // epilogue: relu + NCHW scatter
#pragma unroll
    for (int mt = 0; mt < 2; mt++) {
#pragma unroll
        for (int nt = 0; nt < 4; nt++) {
            int r = m0 + wm * 32 + mt * 16 + (lane >> 2);
            int cc = wn * 32 + nt * 8 + 2 * (lane & 3);
#pragma unroll
            for (int q = 0; q < 4; q++) {
                int rr = r + (q >> 1) * 8;
                int cn = cc + (q & 1);
                float v = fmaxf(acc[mt][nt][q] + bias[cn], 0.f);
                int b = rr / PIX, p = rr % PIX;
                C[((size_t)b * 64 + cn) * PIX + p] = v;
            }
        }
    }
}

// ---------------------------------------------------------------------------
// FC tf32 GEMM, 4-stage pipeline: C[M,N] = A[M,K] * W[N,K]^T + bias
//   M == 128 (grid.x == 1), Ntot % 64 == 0, K % 16 == 0.
//   mode 0: row-major C.  mode 2: scatter into g_hf[0] fragment layout (h0).
// ---------------------------------------------------------------------------
__global__ void __launch_bounds__(256, 1)
gemm_k(const float* __restrict__ A, int lda,
       const float* __restrict__ W, int ldw,
       const float* __restrict__ bias,
       float* __restrict__ C,
       int K, int Ntot, int relu, int mode) {
    extern __shared__ float smx[];
    float* As = smx;
    float* Bs = smx + ENC_STG * ENC_AS;

    int tid = threadIdx.x;
    int warp = tid >> 5, lane = tid & 31;
    int wm = warp >> 1;
    int wn = warp & 1;
    int m0 = blockIdx.x * 128;
    int n0 = blockIdx.y * 64;

    unsigned AsA = (unsigned)__cvta_generic_to_shared(As);
    unsigned BsA = (unsigned)__cvta_generic_to_shared(Bs);

    auto stage = [&](int st, int bf) {
#pragma unroll
        for (int i = 0; i < 2; i++) {
            int e = i * 256 + tid;
            int m = e >> 2, c4 = e & 3;
            cpa16(AsA + (unsigned)(bf * ENC_AS + m * 20 + c4 * 4) * 4,
                  A + (size_t)(m0 + m) * lda + st * 16 + c4 * 4);
        }
        {
            int n = tid >> 2, c4 = tid & 3;
            cpa16(BsA + (unsigned)(bf * ENC_BS + n * 20 + c4 * 4) * 4,
                  W + (size_t)(n0 + n) * ldw + st * 16 + c4 * 4);
        }
        cpa_commit();
    };

    float acc[2][4][4];
#pragma unroll
    for (int a = 0; a < 2; a++)
#pragma unroll
        for (int b = 0; b < 4; b++)
#pragma unroll
            for (int c = 0; c < 4; c++) acc[a][b][c] = 0.f;

    int NIT = K / 16;
    stage(0, 0); stage(1, 1); stage(2, 2);

    for (int it = 0; it < NIT; it++) {
        cpa_wait<2>();
        __syncthreads();
        if (it + 3 < NIT) stage(it + 3, (it + 3) & 3);
        else              cpa_commit();

        const float* Asb = As + (it & 3) * ENC_AS;
        const float* Bsb = Bs + (it & 3) * ENC_BS;
#pragma unroll
        for (int kq = 0; kq < 2; kq++) {
            int kb = kq * 8;
#pragma unroll
            for (int mt = 0; mt < 2; mt++) {
                int r = wm * 32 + mt * 16 + (lane >> 2);
                int c = kb + (lane & 3);
                float a0 = Asb[r * 20 + c];
                float a1 = Asb[(r + 8) * 20 + c];
                float a2 = Asb[r * 20 + c + 4];
                float a3 = Asb[(r + 8) * 20 + c + 4];
#pragma unroll
                for (int nt = 0; nt < 4; nt++) {
                    int n = wn * 32 + nt * 8 + (lane >> 2);
                    float b0 = Bsb[n * 20 + kb + (lane & 3)];
                    float b1 = Bsb[n * 20 + kb + 4 + (lane & 3)];
                    mma8(acc[mt][nt], a0, a1, a2, a3, b0, b1);
                }
            }
        }
    }

#pragma unroll
    for (int mt = 0; mt < 2; mt++) {
#pragma unroll
        for (int nt = 0; nt < 4; nt++) {
            int r = m0 + wm * 32 + mt * 16 + (lane >> 2);
            int cc = n0 + wn * 32 + nt * 8 + 2 * (lane & 3);
#pragma unroll
            for (int q = 0; q < 4; q++) {
                int rr = r + (q >> 1) * 8;
                int cn = cc + (q & 1);
                float v = acc[mt][nt][q] + bias[cn];
                if (relu) v = fmaxf(v, 0.f);
                if (mode == 0) {
                    C[(size_t)rr * Ntot + cn] = v;
                } else {            // h0 -> fragment layout, buffer 0
                    int ib = rr >> 5, bl = rr & 31;
                    g_hf[0][ib * HF_GROUP + hfrag_idx(bl, cn)] = v;
                }
            }
        }
    }
}

// ---------------------------------------------------------------------------
// Persistent GRU. 128 CTAs x 256 threads, 4 independent groups of 32 CTAs.
// h lives in GLOBAL fragment-major layout (g_hf, double buffered):
//   - staging = contiguous 64KB cp.async per CTA per step
//   - mma loop = 1 LDS.128 + nsub LDS.64 per k8 (fragment-major smem)
//   - gates scatter hy directly into next fragment buffer
// gi computed inline from actions (ACT=2).
// ---------------------------------------------------------------------------
#define HSF_FLOATS (2 * 64 * 32 * 4)     // 16384
#define WSF_FLOATS (6 * 64 * 32 * 2)     // 24576
#define GS_FLOATS  (32 * 48)             // 1536
#define GRU_SMEM   ((HSF_FLOATS + WSF_FLOATS + GS_FLOATS) * 4)

__global__ void __launch_bounds__(GTH, 1)
gru_k(const float* __restrict__ actions,
      const float* __restrict__ w_ih,
      const float* __restrict__ w_hh,
      const float* __restrict__ b_ih,
      const float* __restrict__ b_hh,
      float* __restrict__ out,
      float* __restrict__ hT) {
    extern __shared__ float sm[];
    float* HsF = sm;
    float* WsF = sm + HSF_FLOATS;
    float* Gs  = sm + HSF_FLOATS + WSF_FLOATS;

    int tid = threadIdx.x;
    int warp = tid >> 5, lane = tid & 31;
    int wm = warp & 1;
    int wn = warp >> 1;
    int nsub = (wn < 2) ? 2 : 1;
    int sub0 = (wn < 2) ? wn * 2 : wn + 2;

    int cta = blockIdx.x;
    int ib = cta >> 5;
    int jg = cta & 31;
    int j0 = jg * GJT;

    unsigned fbase = *(volatile unsigned*)&g_flag[ib][jg][0];

    // per-thread gate-fusion constants (2 output elements per thread)
    int e0 = tid, e1 = tid + GTH;
    int bl0 = e0 >> 4, jj0 = e0 & 15, bg0 = ib * 32 + bl0, jA = j0 + jj0;
    int bl1 = e1 >> 4, jj1 = e1 & 15, bg1 = ib * 32 + bl1, jB = j0 + jj1;
    int fi0 = hfrag_idx(bl0, jA);
    int fi1 = hfrag_idx(bl1, jB);
    float bhrA = b_hh[jA], bhiA = b_hh[512 + jA], bhnA = b_hh[1024 + jA];
    float bhrB = b_hh[jB], bhiB = b_hh[512 + jB], bhnB = b_hh[1024 + jB];
    float wrA0 = w_ih[2 * jA],          wrA1 = w_ih[2 * jA + 1];
    float wzA0 = w_ih[2 * (512 + jA)],  wzA1 = w_ih[2 * (512 + jA) + 1];
    float wnA0 = w_ih[2 * (1024 + jA)], wnA1 = w_ih[2 * (1024 + jA) + 1];
    float wrB0 = w_ih[2 * jB],          wrB1 = w_ih[2 * jB + 1];
    float wzB0 = w_ih[2 * (512 + jB)],  wzB1 = w_ih[2 * (512 + jB) + 1];
    float wnB0 = w_ih[2 * (1024 + jB)], wnB1 = w_ih[2 * (1024 + jB) + 1];
    float birA = b_ih[jA], bizA = b_ih[512 + jA], binA = b_ih[1024 + jA];
    float birB = b_ih[jB], bizB = b_ih[512 + jB], binB = b_ih[1024 + jB];

    // Stage w_hh fragments once (RNA tf32): WsF[s][k8][lane][2]
#pragma unroll 4
    for (int i = 0; i < 48; i++) {
        int idx = i * GTH + tid;
        int ln = idx & 31;
        int k8 = (idx >> 5) & 63;
        int s  = idx >> 11;               // 0..5
        int n48 = s * 8 + (ln >> 2);
        int gate = n48 >> 4, jj = n48 & 15;
        const float* wrow = w_hh + ((size_t)gate * 512 + j0 + jj) * 512;
        int c = k8 * 8 + (ln & 3);
        float2 bf;
        bf.x = tf32f(wrow[c]);
        bf.y = tf32f(wrow[c + 4]);
        *(float2*)&WsF[(size_t)idx * 2] = bf;
    }

    unsigned HsA = (unsigned)__cvta_generic_to_shared(HsF);

    for (int t = 0; t < TT; t++) {
        const float* hf_cur = &g_hf[t & 1][ib * HF_GROUP];
        float* hf_nxt = &g_hf[(t + 1) & 1][ib * HF_GROUP];

        // prefetch actions + own h values for the gate phase
        const float* ap0 = actions + ((size_t)bg0 * TT + t) * 2;
        const float* ap1 = actions + ((size_t)bg1 * TT + t) * 2;
        float a00 = __ldg(ap0), a01 = __ldg(ap0 + 1);
        float a10 = __ldg(ap1), a11 = __ldg(ap1 + 1);
        float hv0 = __ldcg(hf_cur + fi0);
        float hv1 = __ldcg(hf_cur + fi1);

        // stage full group h tile: contiguous 64KB cp.async
#pragma unroll
        for (int i = 0; i < 16; i++) {
            int e = i * GTH + tid;
            cpa16(HsA + (unsigned)e * 16, hf_cur + (size_t)e * 4);
        }
        cpa_commit();
        cpa_wait<0>();
        __syncthreads();

        float acc[2][4];
#pragma unroll
        for (int a = 0; a < 2; a++)
#pragma unroll
            for (int c = 0; c < 4; c++) acc[a][c] = 0.f;

        const float* afp = HsF + ((size_t)(wm * 64) * 32 + lane) * 4;
        const float* bfp0 = WsF + ((size_t)(sub0 * 64) * 32 + lane) * 2;
        const float* bfp1 = WsF + ((size_t)((sub0 + 1) * 64) * 32 + lane) * 2;

#pragma unroll 8
        for (int k8 = 0; k8 < 64; k8++) {
            float4 af = *(const float4*)(afp + (size_t)k8 * 128);
            float2 b0 = *(const float2*)(bfp0 + (size_t)k8 * 64);
            mma8(acc[0], af.x, af.y, af.z, af.w, b0.x, b0.y);
            if (nsub == 2) {
                float2 b1 = *(const float2*)(bfp1 + (size_t)k8 * 64);
                mma8(acc[1], af.x, af.y, af.z, af.w, b1.x, b1.y);
            }
        }

        // dump gh fragments for gate fusion
#pragma unroll
        for (int i = 0; i < 2; i++) {
            if (i < nsub) {
                int s = sub0 + i;
                int r = wm * 16 + (lane >> 2);
                int c = s * 8 + 2 * (lane & 3);
                Gs[r * 48 + c]           = acc[i][0];
                Gs[r * 48 + c + 1]       = acc[i][1];
                Gs[(r + 8) * 48 + c]     = acc[i][2];
                Gs[(r + 8) * 48 + c + 1] = acc[i][3];
            }
        }
        __syncthreads();

        // fused gates (exact f32 state update; gi inline from actions)
        float hy0, hy1;
        {
            float gr = a00 * wrA0 + a01 * wrA1 + birA;
            float gz = a00 * wzA0 + a01 * wzA1 + bizA;
            float gn = a00 * wnA0 + a01 * wnA1 + binA;
            float ghr = Gs[bl0 * 48 + jj0]      + bhrA;
            float ghi = Gs[bl0 * 48 + 16 + jj0] + bhiA;
            float ghn = Gs[bl0 * 48 + 32 + jj0] + bhnA;
            float r = 1.f / (1.f + expf(-(gr + ghr)));
            float z = 1.f / (1.f + expf(-(gz + ghi)));
            float n = tanhf(gn + r * ghn);
            hy0 = n + z * (hv0 - n);
            hf_nxt[fi0] = hy0;
        }
        {
            float gr = a10 * wrB0 + a11 * wrB1 + birB;
            float gz = a10 * wzB0 + a11 * wzB1 + bizB;
            float gn = a10 * wnB0 + a11 * wnB1 + binB;
            float ghr = Gs[bl1 * 48 + jj1]      + bhrB;
            float ghi = Gs[bl1 * 48 + 16 + jj1] + bhiB;
            float ghn = Gs[bl1 * 48 + 32 + jj1] + bhnB;
            float r = 1.f / (1.f + expf(-(gr + ghr)));
            float z = 1.f / (1.f + expf(-(gz + ghi)));
            float n = tanhf(gn + r * ghn);
            hy1 = n + z * (hv1 - n);
            hf_nxt[fi1] = hy1;
        }

        if (t < TT - 1) {
            // signal, then do output stores off the critical path
            __threadfence();
            __syncthreads();
            if (tid == 0)
                *(volatile unsigned*)&g_flag[ib][jg][0] = fbase + (unsigned)(t + 1);
            out[((size_t)bg0 * TT + t) * HIDN + jA] = hy0;
            out[((size_t)bg1 * TT + t) * HIDN + jB] = hy1;
            if (tid < 32) {
                while ((*(volatile unsigned*)&g_flag[ib][tid][0] - fbase)
                       < (unsigned)(t + 1)) { }
            }
            __syncthreads();
        } else {
            out[((size_t)bg0 * TT + t) * HIDN + jA] = hy0;
            out[((size_t)bg1 * TT + t) * HIDN + jB] = hy1;
            hT[(size_t)bg0 * HIDN + jA] = hy0;
            hT[(size_t)bg1 * HIDN + jB] = hy1;
        }
    }
}

// ---------------------------------------------------------------------------
// Host launch
// ---------------------------------------------------------------------------
extern "C" void kernel_launch(void* const* d_in, const int* in_sizes, int n_in,
                              void* d_out, int out_size) {
    const float* images  = (const float*)d_in[0];
    const float* actions = (const float*)d_in[1];
    const float* cw1 = (const float*)d_in[2];
    const float* cb1 = (const float*)d_in[3];
    const float* cw2 = (const float*)d_in[4];
    const float* cb2 = (const float*)d_in[5];
    const float* cw3 = (const float*)d_in[6];
    const float* cb3 = (const float*)d_in[7];
    const float* fw1 = (const float*)d_in[8];
    const float* fb1 = (const float*)d_in[9];
    const float* fw2 = (const float*)d_in[10];
    const float* fb2 = (const float*)d_in[11];
    const float* fw3 = (const float*)d_in[12];
    const float* fb3 = (const float*)d_in[13];
    const float* w_ih = (const float*)d_in[14];
    const float* w_hh = (const float*)d_in[15];
    const float* b_ih = (const float*)d_in[16];
    const float* b_hh = (const float*)d_in[17];

    float *x1, *x2, *flat, *fc1, *fc2;
    cudaGetSymbolAddress((void**)&x1,   g_x1);
    cudaGetSymbolAddress((void**)&x2,   g_x2);
    cudaGetSymbolAddress((void**)&flat, g_flat);
    cudaGetSymbolAddress((void**)&fc1,  g_fc1);
    cudaGetSymbolAddress((void**)&fc2,  g_fc2);

    cudaFuncSetAttribute(convgemm_k<80, 75, 3, 72, 5, 24>,
                         cudaFuncAttributeMaxDynamicSharedMemorySize, ENC_SMEM);
    cudaFuncSetAttribute(convgemm_k<576, 576, 64, 24, 3, 9>,
                         cudaFuncAttributeMaxDynamicSharedMemorySize, ENC_SMEM);
    cudaFuncSetAttribute(convgemm_k<576, 576, 64, 9, 3, 4>,
                         cudaFuncAttributeMaxDynamicSharedMemorySize, ENC_SMEM);
    cudaFuncSetAttribute(gemm_k,
                         cudaFuncAttributeMaxDynamicSharedMemorySize, ENC_SMEM);
    cudaFuncSetAttribute(gru_k,
                         cudaFuncAttributeMaxDynamicSharedMemorySize, GRU_SMEM);

    // encoder: fused im2col+GEMM convs (4-stage pipelined)
    convgemm_k<80, 75, 3, 72, 5, 24><<<576, 256, ENC_SMEM>>>(images, cw1, cb1, x1);
    convgemm_k<576, 576, 64, 24, 3, 9><<<81, 256, ENC_SMEM>>>(x1, cw2, cb2, x2);
    convgemm_k<576, 576, 64, 9, 3, 4><<<16, 256, ENC_SMEM>>>(x2, cw3, cb3, flat);

    // FC head (4-stage pipelined); fc3 writes h0 in fragment layout (mode 2)
    gemm_k<<<dim3(1, 16), 256, ENC_SMEM>>>(flat, 1024, fw1, 1024, fb1, fc1,
                                           1024, 1024, 1, 0);
    gemm_k<<<dim3(1, 8), 256, ENC_SMEM>>>(fc1, 1024, fw2, 1024, fb2, fc2,
                                          1024, 512, 1, 0);
    gemm_k<<<dim3(1, 8), 256, ENC_SMEM>>>(fc2, 512, fw3, 512, fb3, nullptr,
                                          512, 512, 0, 2);

    // persistent GRU
    float* out = (float*)d_out;
    float* hT = out + (size_t)BB * TT * HIDN;
    gru_k<<<GNC, GTH, GRU_SMEM>>>(actions, w_ih, w_hh, b_ih, b_hh, out, hT);
}

// round 13
// speedup vs baseline: 1.6083x; 1.1216x over previous
#include <cuda_runtime.h>
#include <cstdint>
#include <math.h>

// ---------------------------------------------------------------------------
// Problem constants
// ---------------------------------------------------------------------------
#define BB   128
#define TT   100
#define HIDN 512
#define G3   1536

// GRU tiling
#define GJT  16       // hidden-col tile
#define GNC  128      // CTAs
#define GTH  256      // threads (8 warps)
#define HF_GROUP 16384   // floats per group fragment tile (32x512)

// ---------------------------------------------------------------------------
// Device scratch
// ---------------------------------------------------------------------------
__device__ float g_x1  [(size_t)BB * 64 * 576];   // conv1 out, NCHW
__device__ float g_x2  [(size_t)BB * 64 * 81];    // conv2 out, NCHW
__device__ float g_flat[(size_t)BB * 1024];       // conv3 out == flatten
__device__ float g_fc1 [(size_t)BB * 1024];
__device__ float g_fc2 [(size_t)BB * 512];
__device__ float g_part[(size_t)8 * 128 * 1024];  // split-K partials (4MB)
__device__ __align__(16) float g_hf[2][4 * HF_GROUP];  // h in A-fragment order
__device__ unsigned g_flag[4][32][32];            // [group][cta][pad 128B]

// ---------------------------------------------------------------------------
// Helpers
// ---------------------------------------------------------------------------
__device__ __forceinline__ float tf32f(float x) {
    unsigned u;
    asm("cvt.rna.tf32.f32 %0, %1;" : "=r"(u) : "f"(x));
    return __uint_as_float(u);
}

__device__ __forceinline__ void mma8(float* c,
                                     float a0, float a1, float a2, float a3,
                                     float b0, float b1) {
    unsigned A0 = __float_as_uint(a0), A1 = __float_as_uint(a1);
    unsigned A2 = __float_as_uint(a2), A3 = __float_as_uint(a3);
    unsigned B0 = __float_as_uint(b0), B1 = __float_as_uint(b1);
    asm volatile(
        "mma.sync.aligned.m16n8k8.row.col.f32.tf32.tf32.f32 "
        "{%0,%1,%2,%3}, {%4,%5,%6,%7}, {%8,%9}, {%0,%1,%2,%3};"
        : "+f"(c[0]), "+f"(c[1]), "+f"(c[2]), "+f"(c[3])
        : "r"(A0), "r"(A1), "r"(A2), "r"(A3), "r"(B0), "r"(B1));
}

__device__ __forceinline__ void cpa16(unsigned dst, const void* src) {
    asm volatile("cp.async.cg.shared.global [%0], [%1], 16;\n"
                 :: "r"(dst), "l"(src));
}
__device__ __forceinline__ void cpa_commit() {
    asm volatile("cp.async.commit_group;\n");
}
template<int N> __device__ __forceinline__ void cpa_wait() {
    asm volatile("cp.async.wait_group %0;\n" :: "n"(N));
}

// position of element (bl, j) inside a group's A-fragment tile
__device__ __forceinline__ int hfrag_idx(int bl, int j) {
    int w2 = bl >> 4;
    int k8 = j >> 3;
    int ln = ((bl & 7) << 2) | (j & 3);
    int slot = ((bl >> 3) & 1) | (((j >> 2) & 1) << 1);
    return (((w2 * 64 + k8) << 5) + ln) * 4 + slot;
}

// ---------------------------------------------------------------------------
// Fused im2col + tf32 GEMM conv, 4-stage cp.async pipeline, optional split-K.
//   SPLIT==1: out[b, oc, p] = relu(conv(src) + bias)   (NCHW scatter)
//   SPLIT>1 : partial sums into P[s][m][oc]             (row-major, no bias)
// ---------------------------------------------------------------------------
#define ENC_STG 4
#define ENC_AS  (128 * 20)
#define ENC_BS  (64 * 20)
#define ENC_SMEM ((ENC_STG * (ENC_AS + ENC_BS)) * 4)

template<int KTOT, int KW, int CIN, int IH, int KS, int OW, int SPLIT>
__global__ void __launch_bounds__(256, 1)
convgemm_k(const float* __restrict__ src,
           const float* __restrict__ W,
           const float* __restrict__ bias,
           float* __restrict__ C,
           float* __restrict__ P) {
    constexpr int PIX = OW * OW;
    constexpr int NIT = KTOT / 16 / SPLIT;
    extern __shared__ float smx[];
    float* As = smx;                       // [4][128*20]
    float* Bs = smx + ENC_STG * ENC_AS;    // [4][64*20]

    int tid = threadIdx.x;
    int warp = tid >> 5, lane = tid & 31;
    int wm = warp >> 1;
    int wn = warp & 1;
    int m0 = blockIdx.x * 128;
    int kbase = blockIdx.y * NIT * 16;
    int kk = tid & 15;

    int iy0[8], ix0[8], sb[8], mloc[8];
#pragma unroll
    for (int i = 0; i < 8; i++) {
        mloc[i] = i * 16 + (tid >> 4);
        int m = m0 + mloc[i];
        int b = m / PIX, pix = m % PIX;
        int oy = pix / OW, ox = pix % OW;
        iy0[i] = oy * 3 - 2;
        ix0[i] = ox * 3 - 2;
        sb[i] = b * CIN * IH * IH;
    }

    unsigned AsA = (unsigned)__cvta_generic_to_shared(As);
    unsigned BsA = (unsigned)__cvta_generic_to_shared(Bs);

    auto stage = [&](int st, int bf) {
        int k = kbase + st * 16 + kk;
        bool kok = (k < KW);
        int ci = 0, ky = 0, kx = 0;
        if (kok) {
            ci = k / (KS * KS);
            int rem = k % (KS * KS);
            ky = rem / KS; kx = rem % KS;
        }
#pragma unroll
        for (int i = 0; i < 8; i++) {
            int iy = iy0[i] + ky, ix = ix0[i] + kx;
            bool ok = kok && iy >= 0 && iy < IH && ix >= 0 && ix < IH;
            const float* s = ok ? (src + sb[i] + ((size_t)ci * IH + iy) * IH + ix)
                                : src;
            asm volatile("cp.async.ca.shared.global [%0], [%1], 4, %2;\n"
                         :: "r"(AsA + (unsigned)(bf * ENC_AS + mloc[i] * 20 + kk) * 4),
                            "l"(s), "r"(ok ? 4 : 0));
        }
#pragma unroll
        for (int i = 0; i < 4; i++) {
            int e = i * 256 + tid;
            int n = e >> 4, kl = e & 15;
            int kg = kbase + st * 16 + kl;
            bool ok = (kg < KW);
            const float* s = ok ? (W + (size_t)n * KW + kg) : W;
            asm volatile("cp.async.ca.shared.global [%0], [%1], 4, %2;\n"
                         :: "r"(BsA + (unsigned)(bf * ENC_BS + n * 20 + kl) * 4),
                            "l"(s), "r"(ok ? 4 : 0));
        }
        cpa_commit();
    };

    float acc[2][4][4];
#pragma unroll
    for (int a = 0; a < 2; a++)
#pragma unroll
        for (int b = 0; b < 4; b++)
#pragma unroll
            for (int c = 0; c < 4; c++) acc[a][b][c] = 0.f;

    stage(0, 0);
    if (NIT > 1) stage(1, 1);
    if (NIT > 2) stage(2, 2);

    for (int it = 0; it < NIT; it++) {
        cpa_wait<2>();
        __syncthreads();
        if (it + 3 < NIT) stage(it + 3, (it + 3) & 3);
        else              cpa_commit();          // keep group count advancing

        const float* Asb = As + (it & 3) * ENC_AS;
        const float* Bsb = Bs + (it & 3) * ENC_BS;
#pragma unroll
        for (int kq = 0; kq < 2; kq++) {
            int kb = kq * 8;
#pragma unroll
            for (int mt = 0; mt < 2; mt++) {
                int r = wm * 32 + mt * 16 + (lane >> 2);
                int c = kb + (lane & 3);
                float a0 = Asb[r * 20 + c];
                float a1 = Asb[(r + 8) * 20 + c];
                float a2 = Asb[r * 20 + c + 4];
                float a3 = Asb[(r + 8) * 20 + c + 4];
#pragma unroll
                for (int nt = 0; nt < 4; nt++) {
                    int n = wn * 32 + nt * 8 + (lane >> 2);
                    float b0 = Bsb[n * 20 + kb + (lane & 3)];
                    float b1 = Bsb[n * 20 + kb + 4 + (lane & 3)];
                    mma8(acc[mt][nt], a0, a1, a2, a3, b0, b1);
                }
            }
        }
    }

    // epilogue
#pragma unroll
    for (int mt = 0; mt < 2; mt++) {
#pragma unroll
        for (int nt = 0; nt < 4; nt++) {
            int r = m0 + wm * 32 + mt * 16 + (lane >> 2);
            int cc = wn * 32 + nt * 8 + 2 * (lane & 3);
#pragma unroll
            for (int q = 0; q < 4; q++) {
                int rr = r + (q >> 1) * 8;
                int cn = cc + (q & 1);
                if (SPLIT == 1) {
                    float v = fmaxf(acc[mt][nt][q] + bias[cn], 0.f);
                    int b = rr / PIX, p = rr % PIX;
                    C[((size_t)b * 64 + cn) * PIX + p] = v;
                } else {
                    size_t mtot = (size_t)gridDim.x * 128;
                    P[(size_t)blockIdx.y * mtot * 64 + (size_t)rr * 64 + cn] =
                        acc[mt][nt][q];
                }
            }
        }
    }
}

// conv3 split-K reduce: sum 4 partials + bias + relu + flatten scatter
__global__ void conv3_reduce_k(const float* __restrict__ P,
                               const float* __restrict__ bias) {
    int idx = blockIdx.x * blockDim.x + threadIdx.x;   // < 2048*64
    int rr = idx >> 6, cn = idx & 63;
    const size_t S = (size_t)2048 * 64;
    float v = P[idx] + P[S + idx] + P[2 * S + idx] + P[3 * S + idx];
    v = fmaxf(v + bias[cn], 0.f);
    int b = rr >> 4, p = rr & 15;
    g_flat[(size_t)b * 1024 + cn * 16 + p] = v;
}

// ---------------------------------------------------------------------------
// FC tf32 GEMM, 4-stage pipeline, split-K over blockIdx.z.
// Writes raw partial sums into P[z][m][n] (row-major, no bias).
// ---------------------------------------------------------------------------
__global__ void __launch_bounds__(256, 1)
gemm_k(const float* __restrict__ A, int lda,
       const float* __restrict__ W, int ldw,
       float* __restrict__ P, int nits, int Ntot) {
    extern __shared__ float smx[];
    float* As = smx;
    float* Bs = smx + ENC_STG * ENC_AS;

    int tid = threadIdx.x;
    int warp = tid >> 5, lane = tid & 31;
    int wm = warp >> 1;
    int wn = warp & 1;
    int m0 = blockIdx.x * 128;
    int n0 = blockIdx.y * 64;
    int kbase = blockIdx.z * nits * 16;

    unsigned AsA = (unsigned)__cvta_generic_to_shared(As);
    unsigned BsA = (unsigned)__cvta_generic_to_shared(Bs);

    auto stage = [&](int st, int bf) {
#pragma unroll
        for (int i = 0; i < 2; i++) {
            int e = i * 256 + tid;
            int m = e >> 2, c4 = e & 3;
            cpa16(AsA + (unsigned)(bf * ENC_AS + m * 20 + c4 * 4) * 4,
                  A + (size_t)(m0 + m) * lda + kbase + st * 16 + c4 * 4);
        }
        {
            int n = tid >> 2, c4 = tid & 3;
            cpa16(BsA + (unsigned)(bf * ENC_BS + n * 20 + c4 * 4) * 4,
                  W + (size_t)(n0 + n) * ldw + kbase + st * 16 + c4 * 4);
        }
        cpa_commit();
    };

    float acc[2][4][4];
#pragma unroll
    for (int a = 0; a < 2; a++)
#pragma unroll
        for (int b = 0; b < 4; b++)
#pragma unroll
            for (int c = 0; c < 4; c++) acc[a][b][c] = 0.f;

    stage(0, 0);
    if (nits > 1) stage(1, 1);
    if (nits > 2) stage(2, 2);

    for (int it = 0; it < nits; it++) {
        cpa_wait<2>();
        __syncthreads();
        if (it + 3 < nits) stage(it + 3, (it + 3) & 3);
        else               cpa_commit();

        const float* Asb = As + (it & 3) * ENC_AS;
        const float* Bsb = Bs + (it & 3) * ENC_BS;
#pragma unroll
        for (int kq = 0; kq < 2; kq++) {
            int kb = kq * 8;
#pragma unroll
            for (int mt = 0; mt < 2; mt++) {
                int r = wm * 32 + mt * 16 + (lane >> 2);
                int c = kb + (lane & 3);
                float a0 = Asb[r * 20 + c];
                float a1 = Asb[(r + 8) * 20 + c];
                float a2 = Asb[r * 20 + c + 4];
                float a3 = Asb[(r + 8) * 20 + c + 4];
#pragma unroll
                for (int nt = 0; nt < 4; nt++) {
                    int n = wn * 32 + nt * 8 + (lane >> 2);
                    float b0 = Bsb[n * 20 + kb + (lane & 3)];
                    float b1 = Bsb[n * 20 + kb + 4 + (lane & 3)];
                    mma8(acc[mt][nt], a0, a1, a2, a3, b0, b1);
                }
            }
        }
    }

    size_t poff = (size_t)blockIdx.z * gridDim.x * 128 * Ntot;
#pragma unroll
    for (int mt = 0; mt < 2; mt++) {
#pragma unroll
        for (int nt = 0; nt < 4; nt++) {
            int r = m0 + wm * 32 + mt * 16 + (lane >> 2);
            int cc = n0 + wn * 32 + nt * 8 + 2 * (lane & 3);
#pragma unroll
            for (int q = 0; q < 4; q++) {
                int rr = r + (q >> 1) * 8;
                int cn = cc + (q & 1);
                P[poff + (size_t)rr * Ntot + cn] = acc[mt][nt][q];
            }
        }
    }
}

// FC split-K reduce: sum S partials + bias (+relu); mode 0 row-major out,
// mode 2 scatter into g_hf[0] fragment layout (h0).
__global__ void fc_reduce_k(const float* __restrict__ P, int S, int Ntot,
                            const float* __restrict__ bias, int relu,
                            float* __restrict__ out, int mode) {
    int idx = blockIdx.x * blockDim.x + threadIdx.x;   // < 128*Ntot
    int n = idx % Ntot;
    float v = 0.f;
    size_t stride = (size_t)128 * Ntot;
    for (int s = 0; s < S; s++) v += P[(size_t)s * stride + idx];
    v += bias[n];
    if (relu) v = fmaxf(v, 0.f);
    if (mode == 0) {
        out[idx] = v;
    } else {
        int m = idx / Ntot;
        int ib = m >> 5, bl = m & 31;
        g_hf[0][ib * HF_GROUP + hfrag_idx(bl, n)] = v;
    }
}

// ---------------------------------------------------------------------------
// Persistent GRU. 128 CTAs x 256 threads, 4 independent groups of 32 CTAs.
// h lives in GLOBAL fragment-major layout (g_hf, double buffered).
// Barrier: CG-style release/acquire flags (no per-thread threadfence).
// ---------------------------------------------------------------------------
#define HSF_FLOATS (2 * 64 * 32 * 4)     // 16384
#define WSF_FLOATS (6 * 64 * 32 * 2)     // 24576
#define GS_FLOATS  (32 * 48)             // 1536
#define GRU_SMEM   ((HSF_FLOATS + WSF_FLOATS + GS_FLOATS) * 4)

__global__ void __launch_bounds__(GTH, 1)
gru_k(const float* __restrict__ actions,
      const float* __restrict__ w_ih,
      const float* __restrict__ w_hh,
      const float* __restrict__ b_ih,
      const float* __restrict__ b_hh,
      float* __restrict__ out,
      float* __restrict__ hT) {
    extern __shared__ float sm[];
    float* HsF = sm;
    float* WsF = sm + HSF_FLOATS;
    float* Gs  = sm + HSF_FLOATS + WSF_FLOATS;

    int tid = threadIdx.x;
    int warp = tid >> 5, lane = tid & 31;
    int wm = warp & 1;
    int wn = warp >> 1;
    int nsub = (wn < 2) ? 2 : 1;
    int sub0 = (wn < 2) ? wn * 2 : wn + 2;

    int cta = blockIdx.x;
    int ib = cta >> 5;
    int jg = cta & 31;
    int j0 = jg * GJT;

    unsigned fbase = *(volatile unsigned*)&g_flag[ib][jg][0];

    // per-thread gate-fusion constants (2 output elements per thread)
    int e0 = tid, e1 = tid + GTH;
    int bl0 = e0 >> 4, jj0 = e0 & 15, bg0 = ib * 32 + bl0, jA = j0 + jj0;
    int bl1 = e1 >> 4, jj1 = e1 & 15, bg1 = ib * 32 + bl1, jB = j0 + jj1;
    int fi0 = hfrag_idx(bl0, jA);
    int fi1 = hfrag_idx(bl1, jB);
    float bhrA = b_hh[jA], bhiA = b_hh[512 + jA], bhnA = b_hh[1024 + jA];
    float bhrB = b_hh[jB], bhiB = b_hh[512 + jB], bhnB = b_hh[1024 + jB];
    float wrA0 = w_ih[2 * jA],          wrA1 = w_ih[2 * jA + 1];
    float wzA0 = w_ih[2 * (512 + jA)],  wzA1 = w_ih[2 * (512 + jA) + 1];
    float wnA0 = w_ih[2 * (1024 + jA)], wnA1 = w_ih[2 * (1024 + jA) + 1];
    float wrB0 = w_ih[2 * jB],          wrB1 = w_ih[2 * jB + 1];
    float wzB0 = w_ih[2 * (512 + jB)],  wzB1 = w_ih[2 * (512 + jB) + 1];
    float wnB0 = w_ih[2 * (1024 + jB)], wnB1 = w_ih[2 * (1024 + jB) + 1];
    float birA = b_ih[jA], bizA = b_ih[512 + jA], binA = b_ih[1024 + jA];
    float birB = b_ih[jB], bizB = b_ih[512 + jB], binB = b_ih[1024 + jB];

    // Stage w_hh fragments once (RNA tf32): WsF[s][k8][lane][2]
#pragma unroll 4
    for (int i = 0; i < 48; i++) {
        int idx = i * GTH + tid;
        int ln = idx & 31;
        int k8 = (idx >> 5) & 63;
        int s  = idx >> 11;               // 0..5
        int n48 = s * 8 + (ln >> 2);
        int gate = n48 >> 4, jj = n48 & 15;
        const float* wrow = w_hh + ((size_t)gate * 512 + j0 + jj) * 512;
        int c = k8 * 8 + (ln & 3);
        float2 bf;
        bf.x = tf32f(wrow[c]);
        bf.y = tf32f(wrow[c + 4]);
        *(float2*)&WsF[(size_t)idx * 2] = bf;
    }

    unsigned HsA = (unsigned)__cvta_generic_to_shared(HsF);

    for (int t = 0; t < TT; t++) {
        const float* hf_cur = &g_hf[t & 1][ib * HF_GROUP];
        float* hf_nxt = &g_hf[(t + 1) & 1][ib * HF_GROUP];

        // prefetch actions + own h values for the gate phase
        const float* ap0 = actions + ((size_t)bg0 * TT + t) * 2;
        const float* ap1 = actions + ((size_t)bg1 * TT + t) * 2;
        float a00 = __ldg(ap0), a01 = __ldg(ap0 + 1);
        float a10 = __ldg(ap1), a11 = __ldg(ap1 + 1);
        float hv0 = __ldcg(hf_cur + fi0);
        float hv1 = __ldcg(hf_cur + fi1);

        // stage full group h tile: contiguous 64KB cp.async
#pragma unroll
        for (int i = 0; i < 16; i++) {
            int e = i * GTH + tid;
            cpa16(HsA + (unsigned)e * 16, hf_cur + (size_t)e * 4);
        }
        cpa_commit();
        cpa_wait<0>();
        __syncthreads();

        float acc[2][4];
#pragma unroll
        for (int a = 0; a < 2; a++)
#pragma unroll
            for (int c = 0; c < 4; c++) acc[a][c] = 0.f;

        const float* afp = HsF + ((size_t)(wm * 64) * 32 + lane) * 4;
        const float* bfp0 = WsF + ((size_t)(sub0 * 64) * 32 + lane) * 2;
        const float* bfp1 = WsF + ((size_t)((sub0 + 1) * 64) * 32 + lane) * 2;

#pragma unroll 8
        for (int k8 = 0; k8 < 64; k8++) {
            float4 af = *(const float4*)(afp + (size_t)k8 * 128);
            float2 b0 = *(const float2*)(bfp0 + (size_t)k8 * 64);
            mma8(acc[0], af.x, af.y, af.z, af.w, b0.x, b0.y);
            if (nsub == 2) {
                float2 b1 = *(const float2*)(bfp1 + (size_t)k8 * 64);
                mma8(acc[1], af.x, af.y, af.z, af.w, b1.x, b1.y);
            }
        }

        // dump gh fragments for gate fusion
#pragma unroll
        for (int i = 0; i < 2; i++) {
            if (i < nsub) {
                int s = sub0 + i;
                int r = wm * 16 + (lane >> 2);
                int c = s * 8 + 2 * (lane & 3);
                Gs[r * 48 + c]           = acc[i][0];
                Gs[r * 48 + c + 1]       = acc[i][1];
                Gs[(r + 8) * 48 + c]     = acc[i][2];
                Gs[(r + 8) * 48 + c + 1] = acc[i][3];
            }
        }
        __syncthreads();

        // fused gates (exact f32 state update; gi inline from actions)
        float hy0, hy1;
        {
            float gr = a00 * wrA0 + a01 * wrA1 + birA;
            float gz = a00 * wzA0 + a01 * wzA1 + bizA;
            float gn = a00 * wnA0 + a01 * wnA1 + binA;
            float ghr = Gs[bl0 * 48 + jj0]      + bhrA;
            float ghi = Gs[bl0 * 48 + 16 + jj0] + bhiA;
            float ghn = Gs[bl0 * 48 + 32 + jj0] + bhnA;
            float r = 1.f / (1.f + expf(-(gr + ghr)));
            float z = 1.f / (1.f + expf(-(gz + ghi)));
            float n = tanhf(gn + r * ghn);
            hy0 = n + z * (hv0 - n);
            hf_nxt[fi0] = hy0;
        }
        {
            float gr = a10 * wrB0 + a11 * wrB1 + birB;
            float gz = a10 * wzB0 + a11 * wzB1 + bizB;
            float gn = a10 * wnB0 + a11 * wnB1 + binB;
            float ghr = Gs[bl1 * 48 + jj1]      + bhrB;
            float ghi = Gs[bl1 * 48 + 16 + jj1] + bhiB;
            float ghn = Gs[bl1 * 48 + 32 + jj1] + bhnB;
            float r = 1.f / (1.f + expf(-(gr + ghr)));
            float z = 1.f / (1.f + expf(-(gz + ghi)));
            float n = tanhf(gn + r * ghn);
            hy1 = n + z * (hv1 - n);
            hf_nxt[fi1] = hy1;
        }

        if (t < TT - 1) {
            // CG-style release: bar.sync orders all CTA writes before tid0's
            // release-store; pollers use acquire loads.
            __syncthreads();
            if (tid == 0) {
                unsigned val = fbase + (unsigned)(t + 1);
                asm volatile("st.release.gpu.global.u32 [%0], %1;"
                             :: "l"(&g_flag[ib][jg][0]), "r"(val) : "memory");
            }
            // output stores off the critical path
            out[((size_t)bg0 * TT + t) * HIDN + jA] = hy0;
            out[((size_t)bg1 * TT + t) * HIDN + jB] = hy1;
            if (tid < 32) {
                unsigned target = (unsigned)(t + 1);
                unsigned v;
                do {
                    asm volatile("ld.acquire.gpu.global.u32 %0, [%1];"
                                 : "=r"(v) : "l"(&g_flag[ib][tid][0]) : "memory");
                } while (v - fbase < target);
            }
            __syncthreads();
        } else {
            out[((size_t)bg0 * TT + t) * HIDN + jA] = hy0;
            out[((size_t)bg1 * TT + t) * HIDN + jB] = hy1;
            hT[(size_t)bg0 * HIDN + jA] = hy0;
            hT[(size_t)bg1 * HIDN + jB] = hy1;
        }
    }
}

// ---------------------------------------------------------------------------
// Host launch
// ---------------------------------------------------------------------------
extern "C" void kernel_launch(void* const* d_in, const int* in_sizes, int n_in,
                              void* d_out, int out_size) {
    const float* images  = (const float*)d_in[0];
    const float* actions = (const float*)d_in[1];
    const float* cw1 = (const float*)d_in[2];
    const float* cb1 = (const float*)d_in[3];
    const float* cw2 = (const float*)d_in[4];
    const float* cb2 = (const float*)d_in[5];
    const float* cw3 = (const float*)d_in[6];
    const float* cb3 = (const float*)d_in[7];
    const float* fw1 = (const float*)d_in[8];
    const float* fb1 = (const float*)d_in[9];
    const float* fw2 = (const float*)d_in[10];
    const float* fb2 = (const float*)d_in[11];
    const float* fw3 = (const float*)d_in[12];
    const float* fb3 = (const float*)d_in[13];
    const float* w_ih = (const float*)d_in[14];
    const float* w_hh = (const float*)d_in[15];
    const float* b_ih = (const float*)d_in[16];
    const float* b_hh = (const float*)d_in[17];

    float *x1, *x2, *flat, *fc1, *fc2, *part;
    cudaGetSymbolAddress((void**)&x1,   g_x1);
    cudaGetSymbolAddress((void**)&x2,   g_x2);
    cudaGetSymbolAddress((void**)&flat, g_flat);
    cudaGetSymbolAddress((void**)&fc1,  g_fc1);
    cudaGetSymbolAddress((void**)&fc2,  g_fc2);
    cudaGetSymbolAddress((void**)&part, g_part);

    cudaFuncSetAttribute(convgemm_k<80, 75, 3, 72, 5, 24, 1>,
                         cudaFuncAttributeMaxDynamicSharedMemorySize, ENC_SMEM);
    cudaFuncSetAttribute(convgemm_k<576, 576, 64, 24, 3, 9, 1>,
                         cudaFuncAttributeMaxDynamicSharedMemorySize, ENC_SMEM);
    cudaFuncSetAttribute(convgemm_k<576, 576, 64, 9, 3, 4, 4>,
                         cudaFuncAttributeMaxDynamicSharedMemorySize, ENC_SMEM);
    cudaFuncSetAttribute(gemm_k,
                         cudaFuncAttributeMaxDynamicSharedMemorySize, ENC_SMEM);
    cudaFuncSetAttribute(gru_k,
                         cudaFuncAttributeMaxDynamicSharedMemorySize, GRU_SMEM);

    // encoder: fused im2col+GEMM convs
    convgemm_k<80, 75, 3, 72, 5, 24, 1><<<576, 256, ENC_SMEM>>>(
        images, cw1, cb1, x1, nullptr);
    convgemm_k<576, 576, 64, 24, 3, 9, 1><<<81, 256, ENC_SMEM>>>(
        x1, cw2, cb2, x2, nullptr);
    // conv3 split-K x4 (64 CTAs), then reduce into flatten layout
    convgemm_k<576, 576, 64, 9, 3, 4, 4><<<dim3(16, 4), 256, ENC_SMEM>>>(
        x2, cw3, nullptr, nullptr, part);
    conv3_reduce_k<<<512, 256>>>(part, cb3);

    // FC head: split-K GEMMs + deterministic reduces
    gemm_k<<<dim3(1, 16, 8), 256, ENC_SMEM>>>(flat, 1024, fw1, 1024, part, 8, 1024);
    fc_reduce_k<<<512, 256>>>(part, 8, 1024, fb1, 1, fc1, 0);
    gemm_k<<<dim3(1, 8, 8), 256, ENC_SMEM>>>(fc1, 1024, fw2, 1024, part, 8, 512);
    fc_reduce_k<<<256, 256>>>(part, 8, 512, fb2, 1, fc2, 0);
    gemm_k<<<dim3(1, 8, 4), 256, ENC_SMEM>>>(fc2, 512, fw3, 512, part, 8, 512);
    fc_reduce_k<<<256, 256>>>(part, 4, 512, fb3, 0, nullptr, 2);

    // persistent GRU
    float* out = (float*)d_out;
    float* hT = out + (size_t)BB * TT * HIDN;
    gru_k<<<GNC, GTH, GRU_SMEM>>>(actions, w_ih, w_hh, b_ih, b_hh, out, hT);
}

// round 15
// speedup vs baseline: 1.6795x; 1.0442x over previous
#include <cuda_runtime.h>
#include <cstdint>
#include <math.h>

// ---------------------------------------------------------------------------
// Problem constants
// ---------------------------------------------------------------------------
#define BB   128
#define TT   100
#define HIDN 512
#define G3   1536

// GRU tiling
#define GJT  16       // hidden-col tile
#define GNC  128      // CTAs
#define GTH  256      // threads (8 warps)
#define HF_GROUP 16384   // floats per group fragment tile (32x512)

// ---------------------------------------------------------------------------
// Device scratch
// ---------------------------------------------------------------------------
__device__ float g_x1  [(size_t)BB * 64 * 576];   // conv1 out, NCHW
__device__ float g_x2  [(size_t)BB * 64 * 81];    // conv2 out, NCHW
__device__ float g_flat[(size_t)BB * 1024];       // conv3 out == flatten
__device__ float g_fc1 [(size_t)BB * 1024];
__device__ float g_fc2 [(size_t)BB * 512];
__device__ float g_part[(size_t)8 * 128 * 1024];  // split-K partials (4MB)
__device__ __align__(16) float g_hf[2][4 * HF_GROUP];  // h in A-fragment order
__device__ unsigned g_flag[4][32][32];            // [group][cta][pad 128B]

// ---------------------------------------------------------------------------
// Helpers
// ---------------------------------------------------------------------------
__device__ __forceinline__ float tf32f(float x) {
    unsigned u;
    asm("cvt.rna.tf32.f32 %0, %1;" : "=r"(u) : "f"(x));
    return __uint_as_float(u);
}

__device__ __forceinline__ void mma8(float* c,
                                     float a0, float a1, float a2, float a3,
                                     float b0, float b1) {
    unsigned A0 = __float_as_uint(a0), A1 = __float_as_uint(a1);
    unsigned A2 = __float_as_uint(a2), A3 = __float_as_uint(a3);
    unsigned B0 = __float_as_uint(b0), B1 = __float_as_uint(b1);
    asm volatile(
        "mma.sync.aligned.m16n8k8.row.col.f32.tf32.tf32.f32 "
        "{%0,%1,%2,%3}, {%4,%5,%6,%7}, {%8,%9}, {%0,%1,%2,%3};"
        : "+f"(c[0]), "+f"(c[1]), "+f"(c[2]), "+f"(c[3])
        : "r"(A0), "r"(A1), "r"(A2), "r"(A3), "r"(B0), "r"(B1));
}

__device__ __forceinline__ void cpa16(unsigned dst, const void* src) {
    asm volatile("cp.async.cg.shared.global [%0], [%1], 16;\n"
                 :: "r"(dst), "l"(src));
}
__device__ __forceinline__ void cpa_commit() {
    asm volatile("cp.async.commit_group;\n");
}
template<int N> __device__ __forceinline__ void cpa_wait() {
    asm volatile("cp.async.wait_group %0;\n" :: "n"(N));
}

// fast, saturation-safe gate nonlinearities (~2 ulp; safe at +-inf)
__device__ __forceinline__ float fsigmoid(float x) {
    return __fdividef(1.f, 1.f + __expf(-x));
}
__device__ __forceinline__ float ftanh(float x) {
    return __fdividef(2.f, 1.f + __expf(-2.f * x)) - 1.f;
}

// position of element (bl, j) inside a group's A-fragment tile
__device__ __forceinline__ int hfrag_idx(int bl, int j) {
    int w2 = bl >> 4;
    int k8 = j >> 3;
    int ln = ((bl & 7) << 2) | (j & 3);
    int slot = ((bl >> 3) & 1) | (((j >> 2) & 1) << 1);
    return (((w2 * 64 + k8) << 5) + ln) * 4 + slot;
}

// ---------------------------------------------------------------------------
// Fused im2col + tf32 GEMM conv, 4-stage cp.async pipeline, optional split-K.
// ---------------------------------------------------------------------------
#define ENC_STG 4
#define ENC_AS  (128 * 20)
#define ENC_BS  (64 * 20)
#define ENC_SMEM ((ENC_STG * (ENC_AS + ENC_BS)) * 4)

template<int KTOT, int KW, int CIN, int IH, int KS, int OW, int SPLIT>
__global__ void __launch_bounds__(256, 1)
convgemm_k(const float* __restrict__ src,
           const float* __restrict__ W,
           const float* __restrict__ bias,
           float* __restrict__ C,
           float* __restrict__ P) {
    constexpr int PIX = OW * OW;
    constexpr int NIT = KTOT / 16 / SPLIT;
    extern __shared__ float smx[];
    float* As = smx;                       // [4][128*20]
    float* Bs = smx + ENC_STG * ENC_AS;    // [4][64*20]

    int tid = threadIdx.x;
    int warp = tid >> 5, lane = tid & 31;
    int wm = warp >> 1;
    int wn = warp & 1;
    int m0 = blockIdx.x * 128;
    int kbase = blockIdx.y * NIT * 16;
    int kk = tid & 15;

    int iy0[8], ix0[8], sb[8], mloc[8];
#pragma unroll
    for (int i = 0; i < 8; i++) {
        mloc[i] = i * 16 + (tid >> 4);
        int m = m0 + mloc[i];
        int b = m / PIX, pix = m % PIX;
        int oy = pix / OW, ox = pix % OW;
        iy0[i] = oy * 3 - 2;
        ix0[i] = ox * 3 - 2;
        sb[i] = b * CIN * IH * IH;
    }

    unsigned AsA = (unsigned)__cvta_generic_to_shared(As);
    unsigned BsA = (unsigned)__cvta_generic_to_shared(Bs);

    auto stage = [&](int st, int bf) {
        int k = kbase + st * 16 + kk;
        bool kok = (k < KW);
        int ci = 0, ky = 0, kx = 0;
        if (kok) {
            ci = k / (KS * KS);
            int rem = k % (KS * KS);
            ky = rem / KS; kx = rem % KS;
        }
#pragma unroll
        for (int i = 0; i < 8; i++) {
            int iy = iy0[i] + ky, ix = ix0[i] + kx;
            bool ok = kok && iy >= 0 && iy < IH && ix >= 0 && ix < IH;
            const float* s = ok ? (src + sb[i] + ((size_t)ci * IH + iy) * IH + ix)
                                : src;
            asm volatile("cp.async.ca.shared.global [%0], [%1], 4, %2;\n"
                         :: "r"(AsA + (unsigned)(bf * ENC_AS + mloc[i] * 20 + kk) * 4),
                            "l"(s), "r"(ok ? 4 : 0));
        }
#pragma unroll
        for (int i = 0; i < 4; i++) {
            int e = i * 256 + tid;
            int n = e >> 4, kl = e & 15;
            int kg = kbase + st * 16 + kl;
            bool ok = (kg < KW);
            const float* s = ok ? (W + (size_t)n * KW + kg) : W;
            asm volatile("cp.async.ca.shared.global [%0], [%1], 4, %2;\n"
                         :: "r"(BsA + (unsigned)(bf * ENC_BS + n * 20 + kl) * 4),
                            "l"(s), "r"(ok ? 4 : 0));
        }
        cpa_commit();
    };

    float acc[2][4][4];
#pragma unroll
    for (int a = 0; a < 2; a++)
#pragma unroll
        for (int b = 0; b < 4; b++)
#pragma unroll
            for (int c = 0; c < 4; c++) acc[a][b][c] = 0.f;

    stage(0, 0);
    if (NIT > 1) stage(1, 1);
    if (NIT > 2) stage(2, 2);

    for (int it = 0; it < NIT; it++) {
        cpa_wait<2>();
        __syncthreads();
        if (it + 3 < NIT) stage(it + 3, (it + 3) & 3);
        else              cpa_commit();          // keep group count advancing

        const float* Asb = As + (it & 3) * ENC_AS;
        const float* Bsb = Bs + (it & 3) * ENC_BS;
#pragma unroll
        for (int kq = 0; kq < 2; kq++) {
            int kb = kq * 8;
#pragma unroll
            for (int mt = 0; mt < 2; mt++) {
                int r = wm * 32 + mt * 16 + (lane >> 2);
                int c = kb + (lane & 3);
                float a0 = Asb[r * 20 + c];
                float a1 = Asb[(r + 8) * 20 + c];
                float a2 = Asb[r * 20 + c + 4];
                float a3 = Asb[(r + 8) * 20 + c + 4];
#pragma unroll
                for (int nt = 0; nt < 4; nt++) {
                    int n = wn * 32 + nt * 8 + (lane >> 2);
                    float b0 = Bsb[n * 20 + kb + (lane & 3)];
                    float b1 = Bsb[n * 20 + kb + 4 + (lane & 3)];
                    mma8(acc[mt][nt], a0, a1, a2, a3, b0, b1);
                }
            }
        }
    }

    // epilogue
#pragma unroll
    for (int mt = 0; mt < 2; mt++) {
#pragma unroll
        for (int nt = 0; nt < 4; nt++) {
            int r = m0 + wm * 32 + mt * 16 + (lane >> 2);
            int cc = wn * 32 + nt * 8 + 2 * (lane & 3);
#pragma unroll
            for (int q = 0; q < 4; q++) {
                int rr = r + (q >> 1) * 8;
                int cn = cc + (q & 1);
                if (SPLIT == 1) {
                    float v = fmaxf(acc[mt][nt][q] + bias[cn], 0.f);
                    int b = rr / PIX, p = rr % PIX;
                    C[((size_t)b * 64 + cn) * PIX + p] = v;
                } else {
                    size_t mtot = (size_t)gridDim.x * 128;
                    P[(size_t)blockIdx.y * mtot * 64 + (size_t)rr * 64 + cn] =
                        acc[mt][nt][q];
                }
            }
        }
    }
}

// conv3 split-K reduce: sum 4 partials + bias + relu + flatten scatter
__global__ void conv3_reduce_k(const float* __restrict__ P,
                               const float* __restrict__ bias) {
    int idx = blockIdx.x * blockDim.x + threadIdx.x;   // < 2048*64
    int rr = idx >> 6, cn = idx & 63;
    const size_t S = (size_t)2048 * 64;
    float v = P[idx] + P[S + idx] + P[2 * S + idx] + P[3 * S + idx];
    v = fmaxf(v + bias[cn], 0.f);
    int b = rr >> 4, p = rr & 15;
    g_flat[(size_t)b * 1024 + cn * 16 + p] = v;
}

// ---------------------------------------------------------------------------
// FC tf32 GEMM, 4-stage pipeline, split-K over blockIdx.z.
// ---------------------------------------------------------------------------
__global__ void __launch_bounds__(256, 1)
gemm_k(const float* __restrict__ A, int lda,
       const float* __restrict__ W, int ldw,
       float* __restrict__ P, int nits, int Ntot) {
    extern __shared__ float smx[];
    float* As = smx;
    float* Bs = smx + ENC_STG * ENC_AS;

    int tid = threadIdx.x;
    int warp = tid >> 5, lane = tid & 31;
    int wm = warp >> 1;
    int wn = warp & 1;
    int m0 = blockIdx.x * 128;
    int n0 = blockIdx.y * 64;
    int kbase = blockIdx.z * nits * 16;

    unsigned AsA = (unsigned)__cvta_generic_to_shared(As);
    unsigned BsA = (unsigned)__cvta_generic_to_shared(Bs);

    auto stage = [&](int st, int bf) {
#pragma unroll
        for (int i = 0; i < 2; i++) {
            int e = i * 256 + tid;
            int m = e >> 2, c4 = e & 3;
            cpa16(AsA + (unsigned)(bf * ENC_AS + m * 20 + c4 * 4) * 4,
                  A + (size_t)(m0 + m) * lda + kbase + st * 16 + c4 * 4);
        }
        {
            int n = tid >> 2, c4 = tid & 3;
            cpa16(BsA + (unsigned)(bf * ENC_BS + n * 20 + c4 * 4) * 4,
                  W + (size_t)(n0 + n) * ldw + kbase + st * 16 + c4 * 4);
        }
        cpa_commit();
    };

    float acc[2][4][4];
#pragma unroll
    for (int a = 0; a < 2; a++)
#pragma unroll
        for (int b = 0; b < 4; b++)
#pragma unroll
            for (int c = 0; c < 4; c++) acc[a][b][c] = 0.f;

    stage(0, 0);
    if (nits > 1) stage(1, 1);
    if (nits > 2) stage(2, 2);

    for (int it = 0; it < nits; it++) {
        cpa_wait<2>();
        __syncthreads();
        if (it + 3 < nits) stage(it + 3, (it + 3) & 3);
        else               cpa_commit();

        const float* Asb = As + (it & 3) * ENC_AS;
        const float* Bsb = Bs + (it & 3) * ENC_BS;
#pragma unroll
        for (int kq = 0; kq < 2; kq++) {
            int kb = kq * 8;
#pragma unroll
            for (int mt = 0; mt < 2; mt++) {
                int r = wm * 32 + mt * 16 + (lane >> 2);
                int c = kb + (lane & 3);
                float a0 = Asb[r * 20 + c];
                float a1 = Asb[(r + 8) * 20 + c];
                float a2 = Asb[r * 20 + c + 4];
                float a3 = Asb[(r + 8) * 20 + c + 4];
#pragma unroll
                for (int nt = 0; nt < 4; nt++) {
                    int n = wn * 32 + nt * 8 + (lane >> 2);
                    float b0 = Bsb[n * 20 + kb + (lane & 3)];
                    float b1 = Bsb[n * 20 + kb + 4 + (lane & 3)];
                    mma8(acc[mt][nt], a0, a1, a2, a3, b0, b1);
                }
            }
        }
    }

    size_t poff = (size_t)blockIdx.z * gridDim.x * 128 * Ntot;
#pragma unroll
    for (int mt = 0; mt < 2; mt++) {
#pragma unroll
        for (int nt = 0; nt < 4; nt++) {
            int r = m0 + wm * 32 + mt * 16 + (lane >> 2);
            int cc = n0 + wn * 32 + nt * 8 + 2 * (lane & 3);
#pragma unroll
            for (int q = 0; q < 4; q++) {
                int rr = r + (q >> 1) * 8;
                int cn = cc + (q & 1);
                P[poff + (size_t)rr * Ntot + cn] = acc[mt][nt][q];
            }
        }
    }
}

// FC split-K reduce
__global__ void fc_reduce_k(const float* __restrict__ P, int S, int Ntot,
                            const float* __restrict__ bias, int relu,
                            float* __restrict__ out, int mode) {
    int idx = blockIdx.x * blockDim.x + threadIdx.x;   // < 128*Ntot
    int n = idx % Ntot;
    float v = 0.f;
    size_t stride = (size_t)128 * Ntot;
    for (int s = 0; s < S; s++) v += P[(size_t)s * stride + idx];
    v += bias[n];
    if (relu) v = fmaxf(v, 0.f);
    if (mode == 0) {
        out[idx] = v;
    } else {
        int m = idx / Ntot;
        int ib = m >> 5, bl = m & 31;
        g_hf[0][ib * HF_GROUP + hfrag_idx(bl, n)] = v;
    }
}

// ---------------------------------------------------------------------------
// Persistent GRU. 128 CTAs x 256 threads, 4 independent groups of 32 CTAs.
// h lives in GLOBAL fragment-major layout (g_hf, double buffered).
// Staging is split into two k8-half chunks overlapped with the mma loop.
// Gates use fast saturation-safe __expf-based sigmoid/tanh.
// ---------------------------------------------------------------------------
#define HSF_FLOATS (2 * 64 * 32 * 4)     // 16384
#define WSF_FLOATS (6 * 64 * 32 * 2)     // 24576
#define GS_FLOATS  (32 * 48)             // 1536
#define GRU_SMEM   ((HSF_FLOATS + WSF_FLOATS + GS_FLOATS) * 4)

__global__ void __launch_bounds__(GTH, 1)
gru_k(const float* __restrict__ actions,
      const float* __restrict__ w_ih,
      const float* __restrict__ w_hh,
      const float* __restrict__ b_ih,
      const float* __restrict__ b_hh,
      float* __restrict__ out,
      float* __restrict__ hT) {
    extern __shared__ float sm[];
    float* HsF = sm;
    float* WsF = sm + HSF_FLOATS;
    float* Gs  = sm + HSF_FLOATS + WSF_FLOATS;

    int tid = threadIdx.x;
    int warp = tid >> 5, lane = tid & 31;
    int wm = warp & 1;
    int wn = warp >> 1;
    int nsub = (wn < 2) ? 2 : 1;
    int sub0 = (wn < 2) ? wn * 2 : wn + 2;

    int cta = blockIdx.x;
    int ib = cta >> 5;
    int jg = cta & 31;
    int j0 = jg * GJT;

    unsigned fbase = *(volatile unsigned*)&g_flag[ib][jg][0];

    // per-thread gate-fusion constants (2 output elements per thread)
    int e0 = tid, e1 = tid + GTH;
    int bl0 = e0 >> 4, jj0 = e0 & 15, bg0 = ib * 32 + bl0, jA = j0 + jj0;
    int bl1 = e1 >> 4, jj1 = e1 & 15, bg1 = ib * 32 + bl1, jB = j0 + jj1;
    int fi0 = hfrag_idx(bl0, jA);
    int fi1 = hfrag_idx(bl1, jB);
    float bhrA = b_hh[jA], bhiA = b_hh[512 + jA], bhnA = b_hh[1024 + jA];
    float bhrB = b_hh[jB], bhiB = b_hh[512 + jB], bhnB = b_hh[1024 + jB];
    float wrA0 = w_ih[2 * jA],          wrA1 = w_ih[2 * jA + 1];
    float wzA0 = w_ih[2 * (512 + jA)],  wzA1 = w_ih[2 * (512 + jA) + 1];
    float wnA0 = w_ih[2 * (1024 + jA)], wnA1 = w_ih[2 * (1024 + jA) + 1];
    float wrB0 = w_ih[2 * jB],          wrB1 = w_ih[2 * jB + 1];
    float wzB0 = w_ih[2 * (512 + jB)],  wzB1 = w_ih[2 * (512 + jB) + 1];
    float wnB0 = w_ih[2 * (1024 + jB)], wnB1 = w_ih[2 * (1024 + jB) + 1];
    float birA = b_ih[jA], bizA = b_ih[512 + jA], binA = b_ih[1024 + jA];
    float birB = b_ih[jB], bizB = b_ih[512 + jB], binB = b_ih[1024 + jB];

    // Stage w_hh fragments once (RNA tf32): WsF[s][k8][lane][2]
#pragma unroll 4
    for (int i = 0; i < 48; i++) {
        int idx = i * GTH + tid;
        int ln = idx & 31;
        int k8 = (idx >> 5) & 63;
        int s  = idx >> 11;               // 0..5
        int n48 = s * 8 + (ln >> 2);
        int gate = n48 >> 4, jj = n48 & 15;
        const float* wrow = w_hh + ((size_t)gate * 512 + j0 + jj) * 512;
        int c = k8 * 8 + (ln & 3);
        float2 bf;
        bf.x = tf32f(wrow[c]);
        bf.y = tf32f(wrow[c + 4]);
        *(float2*)&WsF[(size_t)idx * 2] = bf;
    }

    unsigned HsA = (unsigned)__cvta_generic_to_shared(HsF);

    for (int t = 0; t < TT; t++) {
        const float* hf_cur = &g_hf[t & 1][ib * HF_GROUP];
        float* hf_nxt = &g_hf[(t + 1) & 1][ib * HF_GROUP];

        // prefetch actions + own h values for the gate phase
        const float* ap0 = actions + ((size_t)bg0 * TT + t) * 2;
        const float* ap1 = actions + ((size_t)bg1 * TT + t) * 2;
        float a00 = __ldg(ap0), a01 = __ldg(ap0 + 1);
        float a10 = __ldg(ap1), a11 = __ldg(ap1 + 1);
        float hv0 = __ldcg(hf_cur + fi0);
        float hv1 = __ldcg(hf_cur + fi1);

        // stage h tile in two k8-half chunks (overlap 2nd transfer with mma)
        // chunk 0: k8 [0,32) for both wm halves = e [0,1024) u [2048,3072)
#pragma unroll
        for (int i = 0; i < 4; i++) {
            int e = i * GTH + tid;
            cpa16(HsA + (unsigned)e * 16, hf_cur + (size_t)e * 4);
        }
#pragma unroll
        for (int i = 0; i < 4; i++) {
            int e = 2048 + i * GTH + tid;
            cpa16(HsA + (unsigned)e * 16, hf_cur + (size_t)e * 4);
        }
        cpa_commit();
        // chunk 1: k8 [32,64) = e [1024,2048) u [3072,4096)
#pragma unroll
        for (int i = 0; i < 4; i++) {
            int e = 1024 + i * GTH + tid;
            cpa16(HsA + (unsigned)e * 16, hf_cur + (size_t)e * 4);
        }
#pragma unroll
        for (int i = 0; i < 4; i++) {
            int e = 3072 + i * GTH + tid;
            cpa16(HsA + (unsigned)e * 16, hf_cur + (size_t)e * 4);
        }
        cpa_commit();

        float acc[2][4];
#pragma unroll
        for (int a = 0; a < 2; a++)
#pragma unroll
            for (int c = 0; c < 4; c++) acc[a][c] = 0.f;

        const float* afp = HsF + ((size_t)(wm * 64) * 32 + lane) * 4;
        const float* bfp0 = WsF + ((size_t)(sub0 * 64) * 32 + lane) * 2;
        const float* bfp1 = WsF + ((size_t)((sub0 + 1) * 64) * 32 + lane) * 2;

        cpa_wait<1>();
        __syncthreads();
#pragma unroll 8
        for (int k8 = 0; k8 < 32; k8++) {
            float4 af = *(const float4*)(afp + (size_t)k8 * 128);
            float2 b0 = *(const float2*)(bfp0 + (size_t)k8 * 64);
            mma8(acc[0], af.x, af.y, af.z, af.w, b0.x, b0.y);
            if (nsub == 2) {
                float2 b1 = *(const float2*)(bfp1 + (size_t)k8 * 64);
                mma8(acc[1], af.x, af.y, af.z, af.w, b1.x, b1.y);
            }
        }
        cpa_wait<0>();
        __syncthreads();
#pragma unroll 8
        for (int k8 = 32; k8 < 64; k8++) {
            float4 af = *(const float4*)(afp + (size_t)k8 * 128);
            float2 b0 = *(const float2*)(bfp0 + (size_t)k8 * 64);
            mma8(acc[0], af.x, af.y, af.z, af.w, b0.x, b0.y);
            if (nsub == 2) {
                float2 b1 = *(const float2*)(bfp1 + (size_t)k8 * 64);
                mma8(acc[1], af.x, af.y, af.z, af.w, b1.x, b1.y);
            }
        }

        // dump gh fragments for gate fusion
#pragma unroll
        for (int i = 0; i < 2; i++) {
            if (i < nsub) {
                int s = sub0 + i;
                int r = wm * 16 + (lane >> 2);
                int c = s * 8 + 2 * (lane & 3);
                Gs[r * 48 + c]           = acc[i][0];
                Gs[r * 48 + c + 1]       = acc[i][1];
                Gs[(r + 8) * 48 + c]     = acc[i][2];
                Gs[(r + 8) * 48 + c + 1] = acc[i][3];
            }
        }
        __syncthreads();

        // fused gates (exact f32 state update; gi inline from actions)
        float hy0, hy1;
        {
            float gr = a00 * wrA0 + a01 * wrA1 + birA;
            float gz = a00 * wzA0 + a01 * wzA1 + bizA;
            float gn = a00 * wnA0 + a01 * wnA1 + binA;
            float ghr = Gs[bl0 * 48 + jj0]      + bhrA;
            float ghi = Gs[bl0 * 48 + 16 + jj0] + bhiA;
            float ghn = Gs[bl0 * 48 + 32 + jj0] + bhnA;
            float r = fsigmoid(gr + ghr);
            float z = fsigmoid(gz + ghi);
            float n = ftanh(gn + r * ghn);
            hy0 = n + z * (hv0 - n);
            hf_nxt[fi0] = hy0;
        }
        {
            float gr = a10 * wrB0 + a11 * wrB1 + birB;
            float gz = a10 * wzB0 + a11 * wzB1 + bizB;
            float gn = a10 * wnB0 + a11 * wnB1 + binB;
            float ghr = Gs[bl1 * 48 + jj1]      + bhrB;
            float ghi = Gs[bl1 * 48 + 16 + jj1] + bhiB;
            float ghn = Gs[bl1 * 48 + 32 + jj1] + bhnB;
            float r = fsigmoid(gr + ghr);
            float z = fsigmoid(gz + ghi);
            float n = ftanh(gn + r * ghn);
            hy1 = n + z * (hv1 - n);
            hf_nxt[fi1] = hy1;
        }

        if (t < TT - 1) {
            // CG-style release: bar.sync orders all CTA writes before tid0's
            // release-store; pollers use acquire loads.
            __syncthreads();
            if (tid == 0) {
                unsigned val = fbase + (unsigned)(t + 1);
                asm volatile("st.release.gpu.global.u32 [%0], %1;"
                             :: "l"(&g_flag[ib][jg][0]), "r"(val) : "memory");
            }
            // output stores off the critical path
            out[((size_t)bg0 * TT + t) * HIDN + jA] = hy0;
            out[((size_t)bg1 * TT + t) * HIDN + jB] = hy1;
            if (tid < 32) {
                unsigned target = (unsigned)(t + 1);
                unsigned v;
                do {
                    asm volatile("ld.acquire.gpu.global.u32 %0, [%1];"
                                 : "=r"(v) : "l"(&g_flag[ib][tid][0]) : "memory");
                } while (v - fbase < target);
            }
            __syncthreads();
        } else {
            out[((size_t)bg0 * TT + t) * HIDN + jA] = hy0;
            out[((size_t)bg1 * TT + t) * HIDN + jB] = hy1;
            hT[(size_t)bg0 * HIDN + jA] = hy0;
            hT[(size_t)bg1 * HIDN + jB] = hy1;
        }
    }
}

// ---------------------------------------------------------------------------
// Host launch
// ---------------------------------------------------------------------------
extern "C" void kernel_launch(void* const* d_in, const int* in_sizes, int n_in,
                              void* d_out, int out_size) {
    const float* images  = (const float*)d_in[0];
    const float* actions = (const float*)d_in[1];
    const float* cw1 = (const float*)d_in[2];
    const float* cb1 = (const float*)d_in[3];
    const float* cw2 = (const float*)d_in[4];
    const float* cb2 = (const float*)d_in[5];
    const float* cw3 = (const float*)d_in[6];
    const float* cb3 = (const float*)d_in[7];
    const float* fw1 = (const float*)d_in[8];
    const float* fb1 = (const float*)d_in[9];
    const float* fw2 = (const float*)d_in[10];
    const float* fb2 = (const float*)d_in[11];
    const float* fw3 = (const float*)d_in[12];
    const float* fb3 = (const float*)d_in[13];
    const float* w_ih = (const float*)d_in[14];
    const float* w_hh = (const float*)d_in[15];
    const float* b_ih = (const float*)d_in[16];
    const float* b_hh = (const float*)d_in[17];

    float *x1, *x2, *flat, *fc1, *fc2, *part;
    cudaGetSymbolAddress((void**)&x1,   g_x1);
    cudaGetSymbolAddress((void**)&x2,   g_x2);
    cudaGetSymbolAddress((void**)&flat, g_flat);
    cudaGetSymbolAddress((void**)&fc1,  g_fc1);
    cudaGetSymbolAddress((void**)&fc2,  g_fc2);
    cudaGetSymbolAddress((void**)&part, g_part);

    cudaFuncSetAttribute(convgemm_k<80, 75, 3, 72, 5, 24, 1>,
                         cudaFuncAttributeMaxDynamicSharedMemorySize, ENC_SMEM);
    cudaFuncSetAttribute(convgemm_k<576, 576, 64, 24, 3, 9, 1>,
                         cudaFuncAttributeMaxDynamicSharedMemorySize, ENC_SMEM);
    cudaFuncSetAttribute(convgemm_k<576, 576, 64, 9, 3, 4, 4>,
                         cudaFuncAttributeMaxDynamicSharedMemorySize, ENC_SMEM);
    cudaFuncSetAttribute(gemm_k,
                         cudaFuncAttributeMaxDynamicSharedMemorySize, ENC_SMEM);
    cudaFuncSetAttribute(gru_k,
                         cudaFuncAttributeMaxDynamicSharedMemorySize, GRU_SMEM);

    // encoder: fused im2col+GEMM convs
    convgemm_k<80, 75, 3, 72, 5, 24, 1><<<576, 256, ENC_SMEM>>>(
        images, cw1, cb1, x1, nullptr);
    convgemm_k<576, 576, 64, 24, 3, 9, 1><<<81, 256, ENC_SMEM>>>(
        x1, cw2, cb2, x2, nullptr);
    // conv3 split-K x4 (64 CTAs), then reduce into flatten layout
    convgemm_k<576, 576, 64, 9, 3, 4, 4><<<dim3(16, 4), 256, ENC_SMEM>>>(
        x2, cw3, nullptr, nullptr, part);
    conv3_reduce_k<<<512, 256>>>(part, cb3);

    // FC head: split-K GEMMs + deterministic reduces
    gemm_k<<<dim3(1, 16, 8), 256, ENC_SMEM>>>(flat, 1024, fw1, 1024, part, 8, 1024);
    fc_reduce_k<<<512, 256>>>(part, 8, 1024, fb1, 1, fc1, 0);
    gemm_k<<<dim3(1, 8, 8), 256, ENC_SMEM>>>(fc1, 1024, fw2, 1024, part, 8, 512);
    fc_reduce_k<<<256, 256>>>(part, 8, 512, fb2, 1, fc2, 0);
    gemm_k<<<dim3(1, 8, 4), 256, ENC_SMEM>>>(fc2, 512, fw3, 512, part, 8, 512);
    fc_reduce_k<<<256, 256>>>(part, 4, 512, fb3, 0, nullptr, 2);

    // persistent GRU
    float* out = (float*)d_out;
    float* hT = out + (size_t)BB * TT * HIDN;
    gru_k<<<GNC, GTH, GRU_SMEM>>>(actions, w_ih, w_hh, b_ih, b_hh, out, hT);
}

// round 16
// speedup vs baseline: 2.3466x; 1.3972x over previous
#include <cuda_runtime.h>
#include <cstdint>
#include <math.h>

// ---------------------------------------------------------------------------
// Problem constants
// ---------------------------------------------------------------------------
#define BB   128
#define TT   100
#define HIDN 512
#define G3   1536

// GRU tiling
#define GJT  16       // hidden-col tile
#define GNC  128      // CTAs
#define GTH  256      // threads (8 warps; warps 0-3 are mma warps)
#define HF_GROUP 16384   // floats per group fragment tile (32x512)

// ---------------------------------------------------------------------------
// Device scratch
// ---------------------------------------------------------------------------
__device__ float g_x1  [(size_t)BB * 64 * 576];   // conv1 out, NCHW
__device__ float g_x2  [(size_t)BB * 64 * 81];    // conv2 out, NCHW
__device__ float g_flat[(size_t)BB * 1024];       // conv3 out == flatten
__device__ float g_fc1 [(size_t)BB * 1024];
__device__ float g_fc2 [(size_t)BB * 512];
__device__ float g_part[(size_t)8 * 128 * 1024];  // split-K partials (4MB)
__device__ __align__(16) float g_hf[2][4 * HF_GROUP];  // h in A-fragment order
__device__ unsigned g_flag[4][32][32];            // [group][cta][pad 128B]

// ---------------------------------------------------------------------------
// Helpers
// ---------------------------------------------------------------------------
__device__ __forceinline__ float tf32f(float x) {
    unsigned u;
    asm("cvt.rna.tf32.f32 %0, %1;" : "=r"(u) : "f"(x));
    return __uint_as_float(u);
}

__device__ __forceinline__ void mma8(float* c,
                                     float a0, float a1, float a2, float a3,
                                     float b0, float b1) {
    unsigned A0 = __float_as_uint(a0), A1 = __float_as_uint(a1);
    unsigned A2 = __float_as_uint(a2), A3 = __float_as_uint(a3);
    unsigned B0 = __float_as_uint(b0), B1 = __float_as_uint(b1);
    asm volatile(
        "mma.sync.aligned.m16n8k8.row.col.f32.tf32.tf32.f32 "
        "{%0,%1,%2,%3}, {%4,%5,%6,%7}, {%8,%9}, {%0,%1,%2,%3};"
        : "+f"(c[0]), "+f"(c[1]), "+f"(c[2]), "+f"(c[3])
        : "r"(A0), "r"(A1), "r"(A2), "r"(A3), "r"(B0), "r"(B1));
}

__device__ __forceinline__ void cpa16(unsigned dst, const void* src) {
    asm volatile("cp.async.cg.shared.global [%0], [%1], 16;\n"
                 :: "r"(dst), "l"(src));
}
__device__ __forceinline__ void cpa_commit() {
    asm volatile("cp.async.commit_group;\n");
}
template<int N> __device__ __forceinline__ void cpa_wait() {
    asm volatile("cp.async.wait_group %0;\n" :: "n"(N));
}

// fast, saturation-safe gate nonlinearities (~2 ulp; safe at +-inf)
__device__ __forceinline__ float fsigmoid(float x) {
    return __fdividef(1.f, 1.f + __expf(-x));
}
__device__ __forceinline__ float ftanh(float x) {
    return __fdividef(2.f, 1.f + __expf(-2.f * x)) - 1.f;
}

// position of element (bl, j) inside a group's A-fragment tile
__device__ __forceinline__ int hfrag_idx(int bl, int j) {
    int w2 = bl >> 4;
    int k8 = j >> 3;
    int ln = ((bl & 7) << 2) | (j & 3);
    int slot = ((bl >> 3) & 1) | (((j >> 2) & 1) << 1);
    return (((w2 * 64 + k8) << 5) + ln) * 4 + slot;
}

// ---------------------------------------------------------------------------
// Fused im2col + tf32 GEMM conv, 4-stage cp.async pipeline, optional split-K.
// ---------------------------------------------------------------------------
#define ENC_STG 4
#define ENC_AS  (128 * 20)
#define ENC_BS  (64 * 20)
#define ENC_SMEM ((ENC_STG * (ENC_AS + ENC_BS)) * 4)

template<int KTOT, int KW, int CIN, int IH, int KS, int OW, int SPLIT>
__global__ void __launch_bounds__(256, 1)
convgemm_k(const float* __restrict__ src,
           const float* __restrict__ W,
           const float* __restrict__ bias,
           float* __restrict__ C,
           float* __restrict__ P) {
    constexpr int PIX = OW * OW;
    constexpr int NIT = KTOT / 16 / SPLIT;
    extern __shared__ float smx[];
    float* As = smx;                       // [4][128*20]
    float* Bs = smx + ENC_STG * ENC_AS;    // [4][64*20]

    int tid = threadIdx.x;
    int warp = tid >> 5, lane = tid & 31;
    int wm = warp >> 1;
    int wn = warp & 1;
    int m0 = blockIdx.x * 128;
    int kbase = blockIdx.y * NIT * 16;
    int kk = tid & 15;

    int iy0[8], ix0[8], sb[8], mloc[8];
#pragma unroll
    for (int i = 0; i < 8; i++) {
        mloc[i] = i * 16 + (tid >> 4);
        int m = m0 + mloc[i];
        int b = m / PIX, pix = m % PIX;
        int oy = pix / OW, ox = pix % OW;
        iy0[i] = oy * 3 - 2;
        ix0[i] = ox * 3 - 2;
        sb[i] = b * CIN * IH * IH;
    }

    unsigned AsA = (unsigned)__cvta_generic_to_shared(As);
    unsigned BsA = (unsigned)__cvta_generic_to_shared(Bs);

    auto stage = [&](int st, int bf) {
        int k = kbase + st * 16 + kk;
        bool kok = (k < KW);
        int ci = 0, ky = 0, kx = 0;
        if (kok) {
            ci = k / (KS * KS);
            int rem = k % (KS * KS);
            ky = rem / KS; kx = rem % KS;
        }
#pragma unroll
        for (int i = 0; i < 8; i++) {
            int iy = iy0[i] + ky, ix = ix0[i] + kx;
            bool ok = kok && iy >= 0 && iy < IH && ix >= 0 && ix < IH;
            const float* s = ok ? (src + sb[i] + ((size_t)ci * IH + iy) * IH + ix)
                                : src;
            asm volatile("cp.async.ca.shared.global [%0], [%1], 4, %2;\n"
                         :: "r"(AsA + (unsigned)(bf * ENC_AS + mloc[i] * 20 + kk) * 4),
                            "l"(s), "r"(ok ? 4 : 0));
        }
#pragma unroll
        for (int i = 0; i < 4; i++) {
            int e = i * 256 + tid;
            int n = e >> 4, kl = e & 15;
            int kg = kbase + st * 16 + kl;
            bool ok = (kg < KW);
            const float* s = ok ? (W + (size_t)n * KW + kg) : W;
            asm volatile("cp.async.ca.shared.global [%0], [%1], 4, %2;\n"
                         :: "r"(BsA + (unsigned)(bf * ENC_BS + n * 20 + kl) * 4),
                            "l"(s), "r"(ok ? 4 : 0));
        }
        cpa_commit();
    };

    float acc[2][4][4];
#pragma unroll
    for (int a = 0; a < 2; a++)
#pragma unroll
        for (int b = 0; b < 4; b++)
#pragma unroll
            for (int c = 0; c < 4; c++) acc[a][b][c] = 0.f;

    stage(0, 0);
    if (NIT > 1) stage(1, 1);
    if (NIT > 2) stage(2, 2);

    for (int it = 0; it < NIT; it++) {
        cpa_wait<2>();
        __syncthreads();
        if (it + 3 < NIT) stage(it + 3, (it + 3) & 3);
        else              cpa_commit();          // keep group count advancing

        const float* Asb = As + (it & 3) * ENC_AS;
        const float* Bsb = Bs + (it & 3) * ENC_BS;
#pragma unroll
        for (int kq = 0; kq < 2; kq++) {
            int kb = kq * 8;
#pragma unroll
            for (int mt = 0; mt < 2; mt++) {
                int r = wm * 32 + mt * 16 + (lane >> 2);
                int c = kb + (lane & 3);
                float a0 = Asb[r * 20 + c];
                float a1 = Asb[(r + 8) * 20 + c];
                float a2 = Asb[r * 20 + c + 4];
                float a3 = Asb[(r + 8) * 20 + c + 4];
#pragma unroll
                for (int nt = 0; nt < 4; nt++) {
                    int n = wn * 32 + nt * 8 + (lane >> 2);
                    float b0 = Bsb[n * 20 + kb + (lane & 3)];
                    float b1 = Bsb[n * 20 + kb + 4 + (lane & 3)];
                    mma8(acc[mt][nt], a0, a1, a2, a3, b0, b1);
                }
            }
        }
    }

    // epilogue
#pragma unroll
    for (int mt = 0; mt < 2; mt++) {
#pragma unroll
        for (int nt = 0; nt < 4; nt++) {
            int r = m0 + wm * 32 + mt * 16 + (lane >> 2);
            int cc = wn * 32 + nt * 8 + 2 * (lane & 3);
#pragma unroll
            for (int q = 0; q < 4; q++) {
                int rr = r + (q >> 1) * 8;
                int cn = cc + (q & 1);
                if (SPLIT == 1) {
                    float v = fmaxf(acc[mt][nt][q] + bias[cn], 0.f);
                    int b = rr / PIX, p = rr % PIX;
                    C[((size_t)b * 64 + cn) * PIX + p] = v;
                } else {
                    size_t mtot = (size_t)gridDim.x * 128;
                    P[(size_t)blockIdx.y * mtot * 64 + (size_t)rr * 64 + cn] =
                        acc[mt][nt][q];
                }
            }
        }
    }
}

// conv3 split-K reduce: sum 4 partials + bias + relu + flatten scatter
__global__ void conv3_reduce_k(const float* __restrict__ P,
                               const float* __restrict__ bias) {
    int idx = blockIdx.x * blockDim.x + threadIdx.x;   // < 2048*64
    int rr = idx >> 6, cn = idx & 63;
    const size_t S = (size_t)2048 * 64;
    float v = P[idx] + P[S + idx] + P[2 * S + idx] + P[3 * S + idx];
    v = fmaxf(v + bias[cn], 0.f);
    int b = rr >> 4, p = rr & 15;
    g_flat[(size_t)b * 1024 + cn * 16 + p] = v;
}

// ---------------------------------------------------------------------------
// FC tf32 GEMM, 4-stage pipeline, split-K over blockIdx.z.
// ---------------------------------------------------------------------------
__global__ void __launch_bounds__(256, 1)
gemm_k(const float* __restrict__ A, int lda,
       const float* __restrict__ W, int ldw,
       float* __restrict__ P, int nits, int Ntot) {
    extern __shared__ float smx[];
    float* As = smx;
    float* Bs = smx + ENC_STG * ENC_AS;

    int tid = threadIdx.x;
    int warp = tid >> 5, lane = tid & 31;
    int wm = warp >> 1;
    int wn = warp & 1;
    int m0 = blockIdx.x * 128;
    int n0 = blockIdx.y * 64;
    int kbase = blockIdx.z * nits * 16;

    unsigned AsA = (unsigned)__cvta_generic_to_shared(As);
    unsigned BsA = (unsigned)__cvta_generic_to_shared(Bs);

    auto stage = [&](int st, int bf) {
#pragma unroll
        for (int i = 0; i < 2; i++) {
            int e = i * 256 + tid;
            int m = e >> 2, c4 = e & 3;
            cpa16(AsA + (unsigned)(bf * ENC_AS + m * 20 + c4 * 4) * 4,
                  A + (size_t)(m0 + m) * lda + kbase + st * 16 + c4 * 4);
        }
        {
            int n = tid >> 2, c4 = tid & 3;
            cpa16(BsA + (unsigned)(bf * ENC_BS + n * 20 + c4 * 4) * 4,
                  W + (size_t)(n0 + n) * ldw + kbase + st * 16 + c4 * 4);
        }
        cpa_commit();
    };

    float acc[2][4][4];
#pragma unroll
    for (int a = 0; a < 2; a++)
#pragma unroll
        for (int b = 0; b < 4; b++)
#pragma unroll
            for (int c = 0; c < 4; c++) acc[a][b][c] = 0.f;

    stage(0, 0);
    if (nits > 1) stage(1, 1);
    if (nits > 2) stage(2, 2);

    for (int it = 0; it < nits; it++) {
        cpa_wait<2>();
        __syncthreads();
        if (it + 3 < nits) stage(it + 3, (it + 3) & 3);
        else               cpa_commit();

        const float* Asb = As + (it & 3) * ENC_AS;
        const float* Bsb = Bs + (it & 3) * ENC_BS;
#pragma unroll
        for (int kq = 0; kq < 2; kq++) {
            int kb = kq * 8;
#pragma unroll
            for (int mt = 0; mt < 2; mt++) {
                int r = wm * 32 + mt * 16 + (lane >> 2);
                int c = kb + (lane & 3);
                float a0 = Asb[r * 20 + c];
                float a1 = Asb[(r + 8) * 20 + c];
                float a2 = Asb[r * 20 + c + 4];
                float a3 = Asb[(r + 8) * 20 + c + 4];
#pragma unroll
                for (int nt = 0; nt < 4; nt++) {
                    int n = wn * 32 + nt * 8 + (lane >> 2);
                    float b0 = Bsb[n * 20 + kb + (lane & 3)];
                    float b1 = Bsb[n * 20 + kb + 4 + (lane & 3)];
                    mma8(acc[mt][nt], a0, a1, a2, a3, b0, b1);
                }
            }
        }
    }

    size_t poff = (size_t)blockIdx.z * gridDim.x * 128 * Ntot;
#pragma unroll
    for (int mt = 0; mt < 2; mt++) {
#pragma unroll
        for (int nt = 0; nt < 4; nt++) {
            int r = m0 + wm * 32 + mt * 16 + (lane >> 2);
            int cc = n0 + wn * 32 + nt * 8 + 2 * (lane & 3);
#pragma unroll
            for (int q = 0; q < 4; q++) {
                int rr = r + (q >> 1) * 8;
                int cn = cc + (q & 1);
                P[poff + (size_t)rr * Ntot + cn] = acc[mt][nt][q];
            }
        }
    }
}

// FC split-K reduce
__global__ void fc_reduce_k(const float* __restrict__ P, int S, int Ntot,
                            const float* __restrict__ bias, int relu,
                            float* __restrict__ out, int mode) {
    int idx = blockIdx.x * blockDim.x + threadIdx.x;   // < 128*Ntot
    int n = idx % Ntot;
    float v = 0.f;
    size_t stride = (size_t)128 * Ntot;
    for (int s = 0; s < S; s++) v += P[(size_t)s * stride + idx];
    v += bias[n];
    if (relu) v = fmaxf(v, 0.f);
    if (mode == 0) {
        out[idx] = v;
    } else {
        int m = idx / Ntot;
        int ib = m >> 5, bl = m & 31;
        g_hf[0][ib * HF_GROUP + hfrag_idx(bl, n)] = v;
    }
}

// ---------------------------------------------------------------------------
// Persistent GRU. 128 CTAs x 256 threads, 4 independent groups of 32 CTAs.
// NEW: 4 mma warps (one/SMSP), each computes the FULL m32 x n48 tile over a
// private k-quarter (k8 in [16w, 16w+16)); A and B fragments read from smem
// exactly ONCE (160KB/step vs 448KB before). Each mma warp stages its own
// k-slice via cp.async (lane reads only what it staged: no intra-CTA sync),
// and polls only the 8 producer-CTA flags its k-slice depends on.
// Partial accumulators are summed across the 4 warps in the gate phase.
// ---------------------------------------------------------------------------
#define HSF_FLOATS (2 * 64 * 32 * 4)     // 16384
#define WSF_FLOATS (6 * 64 * 32 * 2)     // 24576
#define GS_FLOATS  (4 * 32 * 48)         // 6144
#define GRU_SMEM   ((HSF_FLOATS + WSF_FLOATS + GS_FLOATS) * 4)

__global__ void __launch_bounds__(GTH, 1)
gru_k(const float* __restrict__ actions,
      const float* __restrict__ w_ih,
      const float* __restrict__ w_hh,
      const float* __restrict__ b_ih,
      const float* __restrict__ b_hh,
      float* __restrict__ out,
      float* __restrict__ hT) {
    extern __shared__ float sm[];
    float* HsF = sm;
    float* WsF = sm + HSF_FLOATS;
    float* Gs  = sm + HSF_FLOATS + WSF_FLOATS;   // [4][32][48]

    int tid = threadIdx.x;
    int warp = tid >> 5, lane = tid & 31;

    int cta = blockIdx.x;
    int ib = cta >> 5;
    int jg = cta & 31;
    int j0 = jg * GJT;

    unsigned fbase = *(volatile unsigned*)&g_flag[ib][jg][0];

    // per-thread gate-fusion constants (2 output elements per thread)
    int e0 = tid, e1 = tid + GTH;
    int bl0 = e0 >> 4, jj0 = e0 & 15, bg0 = ib * 32 + bl0, jA = j0 + jj0;
    int bl1 = e1 >> 4, jj1 = e1 & 15, bg1 = ib * 32 + bl1, jB = j0 + jj1;
    int fi0 = hfrag_idx(bl0, jA);
    int fi1 = hfrag_idx(bl1, jB);
    float bhrA = b_hh[jA], bhiA = b_hh[512 + jA], bhnA = b_hh[1024 + jA];
    float bhrB = b_hh[jB], bhiB = b_hh[512 + jB], bhnB = b_hh[1024 + jB];
    float wrA0 = w_ih[2 * jA],          wrA1 = w_ih[2 * jA + 1];
    float wzA0 = w_ih[2 * (512 + jA)],  wzA1 = w_ih[2 * (512 + jA) + 1];
    float wnA0 = w_ih[2 * (1024 + jA)], wnA1 = w_ih[2 * (1024 + jA) + 1];
    float wrB0 = w_ih[2 * jB],          wrB1 = w_ih[2 * jB + 1];
    float wzB0 = w_ih[2 * (512 + jB)],  wzB1 = w_ih[2 * (512 + jB) + 1];
    float wnB0 = w_ih[2 * (1024 + jB)], wnB1 = w_ih[2 * (1024 + jB) + 1];
    float birA = b_ih[jA], bizA = b_ih[512 + jA], binA = b_ih[1024 + jA];
    float birB = b_ih[jB], bizB = b_ih[512 + jB], binB = b_ih[1024 + jB];

    // Stage w_hh fragments once (RNA tf32): WsF[s][k8][lane][2]
#pragma unroll 4
    for (int i = 0; i < 48; i++) {
        int idx = i * GTH + tid;
        int ln = idx & 31;
        int k8 = (idx >> 5) & 63;
        int s  = idx >> 11;               // 0..5
        int n48 = s * 8 + (ln >> 2);
        int gate = n48 >> 4, jj = n48 & 15;
        const float* wrow = w_hh + ((size_t)gate * 512 + j0 + jj) * 512;
        int c = k8 * 8 + (ln & 3);
        float2 bf;
        bf.x = tf32f(wrow[c]);
        bf.y = tf32f(wrow[c + 4]);
        *(float2*)&WsF[(size_t)idx * 2] = bf;
    }
    __syncthreads();   // WsF visible to mma warps before t=0

    unsigned HsA = (unsigned)__cvta_generic_to_shared(HsF);
    const unsigned* myflags = &g_flag[ib][0][0];   // stride 32 unsigneds per cta

    for (int t = 0; t < TT; t++) {
        const float* hf_cur = &g_hf[t & 1][ib * HF_GROUP];
        float* hf_nxt = &g_hf[(t + 1) & 1][ib * HF_GROUP];

        // prefetch actions + own h values for the gate phase (own columns:
        // written by THIS cta last step, no flag needed)
        const float* ap0 = actions + ((size_t)bg0 * TT + t) * 2;
        const float* ap1 = actions + ((size_t)bg1 * TT + t) * 2;
        float a00 = __ldg(ap0), a01 = __ldg(ap0 + 1);
        float a10 = __ldg(ap1), a11 = __ldg(ap1 + 1);
        float hv0 = __ldcg(hf_cur + fi0);
        float hv1 = __ldcg(hf_cur + fi1);

        if (warp < 4) {
            int w = warp;
            int kb0 = w * 16;
            // fine-grained dependency wait: only the 8 producer CTAs whose
            // columns [128w, 128w+128) this warp's k-slice reads
            if (t > 0) {
                if (lane < 8) {
                    const unsigned* fp = myflags + (8 * w + lane) * 32;
                    unsigned v;
                    do {
                        asm volatile("ld.acquire.gpu.global.u32 %0, [%1];"
                                     : "=r"(v) : "l"(fp) : "memory");
                    } while (v - fbase < (unsigned)t);
                }
                __syncwarp();
            }
            // stage own k-slice (16KB) in 2 chunks; each lane reads back only
            // its own staged addresses -> no cross-thread sync needed
#pragma unroll
            for (int ch = 0; ch < 2; ch++) {
#pragma unroll
                for (int q = 0; q < 8; q++) {
                    int k8 = kb0 + ch * 8 + q;
                    int i0 = (k8 << 5) + lane;
                    int i1 = ((64 + k8) << 5) + lane;
                    cpa16(HsA + (unsigned)i0 * 16, hf_cur + (size_t)i0 * 4);
                    cpa16(HsA + (unsigned)i1 * 16, hf_cur + (size_t)i1 * 4);
                }
                cpa_commit();
            }

            float acc[2][6][4];
#pragma unroll
            for (int m2 = 0; m2 < 2; m2++)
#pragma unroll
                for (int s = 0; s < 6; s++)
#pragma unroll
                    for (int q = 0; q < 4; q++) acc[m2][s][q] = 0.f;

            cpa_wait<1>();
#pragma unroll
            for (int q = 0; q < 8; q++) {
                int k8 = kb0 + q;
                float4 af0 = *(const float4*)(HsF + (((size_t)k8 << 5) + lane) * 4);
                float4 af1 = *(const float4*)(HsF + ((((size_t)64 + k8) << 5) + lane) * 4);
#pragma unroll
                for (int s = 0; s < 6; s++) {
                    float2 b = *(const float2*)(WsF + (((size_t)(s * 64 + k8) << 5) + lane) * 2);
                    mma8(acc[0][s], af0.x, af0.y, af0.z, af0.w, b.x, b.y);
                    mma8(acc[1][s], af1.x, af1.y, af1.z, af1.w, b.x, b.y);
                }
            }
            cpa_wait<0>();
#pragma unroll
            for (int q = 8; q < 16; q++) {
                int k8 = kb0 + q;
                float4 af0 = *(const float4*)(HsF + (((size_t)k8 << 5) + lane) * 4);
                float4 af1 = *(const float4*)(HsF + ((((size_t)64 + k8) << 5) + lane) * 4);
#pragma unroll
                for (int s = 0; s < 6; s++) {
                    float2 b = *(const float2*)(WsF + (((size_t)(s * 64 + k8) << 5) + lane) * 2);
                    mma8(acc[0][s], af0.x, af0.y, af0.z, af0.w, b.x, b.y);
                    mma8(acc[1][s], af1.x, af1.y, af1.z, af1.w, b.x, b.y);
                }
            }

            // dump partials: Gs[w][r][c]
            float* gw = Gs + w * (32 * 48);
            int rb = (lane >> 2);
            int cb = 2 * (lane & 3);
#pragma unroll
            for (int m2 = 0; m2 < 2; m2++) {
#pragma unroll
                for (int s = 0; s < 6; s++) {
                    int r = m2 * 16 + rb;
                    int c = s * 8 + cb;
                    *(float2*)&gw[r * 48 + c] =
                        make_float2(acc[m2][s][0], acc[m2][s][1]);
                    *(float2*)&gw[(r + 8) * 48 + c] =
                        make_float2(acc[m2][s][2], acc[m2][s][3]);
                }
            }
        }
        __syncthreads();

        // fused gates: sum 4 k-partials, exact f32 state update
        float hy0, hy1;
        {
            int o = bl0 * 48 + jj0;
            float ghr = Gs[o] + Gs[1536 + o] + Gs[3072 + o] + Gs[4608 + o] + bhrA;
            o += 16;
            float ghi = Gs[o] + Gs[1536 + o] + Gs[3072 + o] + Gs[4608 + o] + bhiA;
            o += 16;
            float ghn = Gs[o] + Gs[1536 + o] + Gs[3072 + o] + Gs[4608 + o] + bhnA;
            float gr = a00 * wrA0 + a01 * wrA1 + birA;
            float gz = a00 * wzA0 + a01 * wzA1 + bizA;
            float gn = a00 * wnA0 + a01 * wnA1 + binA;
            float r = fsigmoid(gr + ghr);
            float z = fsigmoid(gz + ghi);
            float n = ftanh(gn + r * ghn);
            hy0 = n + z * (hv0 - n);
            hf_nxt[fi0] = hy0;
        }
        {
            int o = bl1 * 48 + jj1;
            float ghr = Gs[o] + Gs[1536 + o] + Gs[3072 + o] + Gs[4608 + o] + bhrB;
            o += 16;
            float ghi = Gs[o] + Gs[1536 + o] + Gs[3072 + o] + Gs[4608 + o] + bhiB;
            o += 16;
            float ghn = Gs[o] + Gs[1536 + o] + Gs[3072 + o] + Gs[4608 + o] + bhnB;
            float gr = a10 * wrB0 + a11 * wrB1 + birB;
            float gz = a10 * wzB0 + a11 * wzB1 + bizB;
            float gn = a10 * wnB0 + a11 * wnB1 + binB;
            float r = fsigmoid(gr + ghr);
            float z = fsigmoid(gz + ghi);
            float n = ftanh(gn + r * ghn);
            hy1 = n + z * (hv1 - n);
            hf_nxt[fi1] = hy1;
        }

        // all hy stores done before release; also protects Gs for next step
        __syncthreads();

        if (t < TT - 1) {
            if (tid == 0) {
                unsigned val = fbase + (unsigned)(t + 1);
                asm volatile("st.release.gpu.global.u32 [%0], %1;"
                             :: "l"(&g_flag[ib][jg][0]), "r"(val) : "memory");
            }
            // output stores off the critical path
            out[((size_t)bg0 * TT + t) * HIDN + jA] = hy0;
            out[((size_t)bg1 * TT + t) * HIDN + jB] = hy1;
        } else {
            out[((size_t)bg0 * TT + t) * HIDN + jA] = hy0;
            out[((size_t)bg1 * TT + t) * HIDN + jB] = hy1;
            hT[(size_t)bg0 * HIDN + jA] = hy0;
            hT[(size_t)bg1 * HIDN + jB] = hy1;
        }
    }
}

// ---------------------------------------------------------------------------
// Host launch
// ---------------------------------------------------------------------------
extern "C" void kernel_launch(void* const* d_in, const int* in_sizes, int n_in,
                              void* d_out, int out_size) {
    const float* images  = (const float*)d_in[0];
    const float* actions = (const float*)d_in[1];
    const float* cw1 = (const float*)d_in[2];
    const float* cb1 = (const float*)d_in[3];
    const float* cw2 = (const float*)d_in[4];
    const float* cb2 = (const float*)d_in[5];
    const float* cw3 = (const float*)d_in[6];
    const float* cb3 = (const float*)d_in[7];
    const float* fw1 = (const float*)d_in[8];
    const float* fb1 = (const float*)d_in[9];
    const float* fw2 = (const float*)d_in[10];
    const float* fb2 = (const float*)d_in[11];
    const float* fw3 = (const float*)d_in[12];
    const float* fb3 = (const float*)d_in[13];
    const float* w_ih = (const float*)d_in[14];
    const float* w_hh = (const float*)d_in[15];
    const float* b_ih = (const float*)d_in[16];
    const float* b_hh = (const float*)d_in[17];

    float *x1, *x2, *flat, *fc1, *fc2, *part;
    cudaGetSymbolAddress((void**)&x1,   g_x1);
    cudaGetSymbolAddress((void**)&x2,   g_x2);
    cudaGetSymbolAddress((void**)&flat, g_flat);
    cudaGetSymbolAddress((void**)&fc1,  g_fc1);
    cudaGetSymbolAddress((void**)&fc2,  g_fc2);
    cudaGetSymbolAddress((void**)&part, g_part);

    cudaFuncSetAttribute(convgemm_k<80, 75, 3, 72, 5, 24, 1>,
                         cudaFuncAttributeMaxDynamicSharedMemorySize, ENC_SMEM);
    cudaFuncSetAttribute(convgemm_k<576, 576, 64, 24, 3, 9, 1>,
                         cudaFuncAttributeMaxDynamicSharedMemorySize, ENC_SMEM);
    cudaFuncSetAttribute(convgemm_k<576, 576, 64, 9, 3, 4, 4>,
                         cudaFuncAttributeMaxDynamicSharedMemorySize, ENC_SMEM);
    cudaFuncSetAttribute(gemm_k,
                         cudaFuncAttributeMaxDynamicSharedMemorySize, ENC_SMEM);
    cudaFuncSetAttribute(gru_k,
                         cudaFuncAttributeMaxDynamicSharedMemorySize, GRU_SMEM);

    // encoder: fused im2col+GEMM convs
    convgemm_k<80, 75, 3, 72, 5, 24, 1><<<576, 256, ENC_SMEM>>>(
        images, cw1, cb1, x1, nullptr);
    convgemm_k<576, 576, 64, 24, 3, 9, 1><<<81, 256, ENC_SMEM>>>(
        x1, cw2, cb2, x2, nullptr);
    // conv3 split-K x4 (64 CTAs), then reduce into flatten layout
    convgemm_k<576, 576, 64, 9, 3, 4, 4><<<dim3(16, 4), 256, ENC_SMEM>>>(
        x2, cw3, nullptr, nullptr, part);
    conv3_reduce_k<<<512, 256>>>(part, cb3);

    // FC head: split-K GEMMs + deterministic reduces
    gemm_k<<<dim3(1, 16, 8), 256, ENC_SMEM>>>(flat, 1024, fw1, 1024, part, 8, 1024);
    fc_reduce_k<<<512, 256>>>(part, 8, 1024, fb1, 1, fc1, 0);
    gemm_k<<<dim3(1, 8, 8), 256, ENC_SMEM>>>(fc1, 1024, fw2, 1024, part, 8, 512);
    fc_reduce_k<<<256, 256>>>(part, 8, 512, fb2, 1, fc2, 0);
    gemm_k<<<dim3(1, 8, 4), 256, ENC_SMEM>>>(fc2, 512, fw3, 512, part, 8, 512);
    fc_reduce_k<<<256, 256>>>(part, 4, 512, fb3, 0, nullptr, 2);

    // persistent GRU
    float* out = (float*)d_out;
    float* hT = out + (size_t)BB * TT * HIDN;
    gru_k<<<GNC, GTH, GRU_SMEM>>>(actions, w_ih, w_hh, b_ih, b_hh, out, hT);
}